// round 5
// baseline (speedup 1.0000x reference)
#include <cuda_runtime.h>
#include <cuda_fp16.h>
#include <cstdint>
#include <math.h>

// Problem constants
constexpr int   D       = 2048;
constexpr int   F       = 256;
constexpr float ALPHA   = 0.005f;   // SINKHORN_ALPHA
constexpr float STOPTHR = 0.005f;
constexpr float EPSF    = 1e-16f;
constexpr int   MAXIT   = 500;

// Launch shapes
constexpr int NB   = 128;         // persistent sinkhorn blocks
constexpr int NT   = 256;
constexpr int RPB  = D / NB;      // 16 rows per block
constexpr int NKB  = 256;
constexpr int NBLK = 136;         // triangular 128x128 tile count: 16*17/2

typedef unsigned long long ull;

// ---------------- device scratch ----------------
__device__ __half d_Kh[(size_t)D * D];    // 8 MB: K = exp(-alpha*C), fp16, symmetric
__device__ float  d_G[(size_t)D * D];     // 16 MB: Ghat = ehat ehat^T, symmetric
__device__ float  d_ehat[D * F];
__device__ float  d_sq[D];
__device__ float  d_invr[D];
__device__ float  d_u[D];
__device__ float  d_v[D];
__device__ float  d_errpart[12 * NB];
__device__ double d_part[3 * NKB];
__device__ unsigned d_flags[NB];

// ---------------- f32x2 helpers (FFMA2 — only reachable via PTX) ----------------
__device__ __forceinline__ ull pk2(float lo, float hi) {
    ull r; asm("mov.b64 %0,{%1,%2};" : "=l"(r) : "f"(lo), "f"(hi)); return r;
}
__device__ __forceinline__ float2 up2(ull v) {
    float2 f; asm("mov.b64 {%0,%1},%2;" : "=f"(f.x), "=f"(f.y) : "l"(v)); return f;
}
__device__ __forceinline__ void fma2(ull& d, ull a, ull b) {
    asm("fma.rn.f32x2 %0,%1,%2,%0;" : "+l"(d) : "l"(a), "l"(b));
}
// half2 (as u32) -> packed f32x2 (as u64)
__device__ __forceinline__ ull h2f2(unsigned h) {
    const float2 f = __half22float2(*reinterpret_cast<const __half2*>(&h));
    return pk2(f.x, f.y);
}

__device__ __forceinline__ float warp_red(float s) {
#pragma unroll
    for (int o = 16; o; o >>= 1) s += __shfl_xor_sync(0xffffffffu, s, o);
    return s;
}

// Distributed flag grid barrier (release store, all-flags poll in warp 0)
__device__ __forceinline__ void gbar(unsigned ep, int tid, int bid) {
    __syncthreads();
    if (tid == 0) {
        __threadfence();
        __stcg(&d_flags[bid], ep);
    }
    if (tid < 32) {
        const int lane = tid;
        for (;;) {
            int ok = 1;
#pragma unroll
            for (int k = 0; k < NB / 32; k++)
                if (__ldcg(&d_flags[lane * (NB / 32) + k]) < ep) ok = 0;
            if (__all_sync(0xffffffffu, ok)) break;
            __nanosleep(20);
        }
        __threadfence();
    }
    __syncthreads();
}

// ---------------- prep: sq, ehat, flag reset ----------------
__global__ void __launch_bounds__(F) prep(const float* __restrict__ theta,
                                          const float* __restrict__ emb) {
    const int row = blockIdx.x, tid = threadIdx.x;
    if (tid == 0 && row < NB) d_flags[row] = 0u;

    const float t = theta[row * F + tid];
    const float e = emb[row * F + tid];
    float a = t * t, b = e * e;
#pragma unroll
    for (int o = 16; o; o >>= 1) {
        a += __shfl_xor_sync(0xffffffffu, a, o);
        b += __shfl_xor_sync(0xffffffffu, b, o);
    }
    __shared__ float sa[8], sb[8];
    __shared__ float s_inv;
    const int wid = tid >> 5, lane = tid & 31;
    if (lane == 0) { sa[wid] = a; sb[wid] = b; }
    __syncthreads();
    if (tid == 0) {
        float ta = 0.f, tb = 0.f;
#pragma unroll
        for (int i = 0; i < 8; i++) { ta += sa[i]; tb += sb[i]; }
        d_sq[row] = ta;
        s_inv = 1.0f / sqrtf(tb);
    }
    __syncthreads();
    d_ehat[row * F + tid] = e * s_inv;
}

// ---------------- symmetric fused GEMM (f32x2 microkernel) --------------
// bid in [0, NBLK)      : K (fp16 out) = exp(-alpha*max(sq_i+sq_j-2*theta theta^T,0))
// bid in [NBLK, 2*NBLK) : Ghat (fp32 out) = ehat ehat^T
// 128x128 tile, 8x8 per thread, lower-triangle blocks, mirror store.
__global__ void __launch_bounds__(256, 2) gemm_sym(const float* __restrict__ theta) {
    const int bid = blockIdx.x;
    const bool modeK = (bid < NBLK);
    const int tb = modeK ? bid : bid - NBLK;
    const float* __restrict__ X = modeK ? theta : (const float*)d_ehat;

    // triangular index -> (ib, jb), ib >= jb
    int ib = (int)((sqrtf(8.0f * (float)tb + 1.0f) - 1.0f) * 0.5f);
    while ((ib + 1) * (ib + 2) / 2 <= tb) ib++;
    while (ib * (ib + 1) / 2 > tb) ib--;
    const int jb = tb - ib * (ib + 1) / 2;

    __shared__ float Asd[16][256];   // A values duplicated: Asd[kk][2r]=Asd[kk][2r+1]
    __shared__ float Bs[16][128];
    const int tid = threadIdx.x;
    const int tx = tid & 15, ty = tid >> 4;
    const int r0 = ib * 128, c0 = jb * 128;

    ull acc[8][4];
#pragma unroll
    for (int i = 0; i < 8; i++)
#pragma unroll
        for (int j = 0; j < 4; j++) acc[i][j] = 0ULL;

    for (int k0 = 0; k0 < F; k0 += 16) {
#pragma unroll
        for (int q = 0; q < 2; q++) {
            const int idx = tid * 2 + q;        // 0..511
            const int row = idx >> 2;           // 0..127
            const int kk  = (idx & 3) * 4;      // 0,4,8,12
            const float4 av = *(const float4*)(X + (size_t)(r0 + row) * F + k0 + kk);
            *(float2*)&Asd[kk + 0][2 * row] = make_float2(av.x, av.x);
            *(float2*)&Asd[kk + 1][2 * row] = make_float2(av.y, av.y);
            *(float2*)&Asd[kk + 2][2 * row] = make_float2(av.z, av.z);
            *(float2*)&Asd[kk + 3][2 * row] = make_float2(av.w, av.w);
            const float4 bv = *(const float4*)(X + (size_t)(c0 + row) * F + k0 + kk);
            Bs[kk + 0][row] = bv.x; Bs[kk + 1][row] = bv.y;
            Bs[kk + 2][row] = bv.z; Bs[kk + 3][row] = bv.w;
        }
        __syncthreads();
#pragma unroll
        for (int kk = 0; kk < 16; kk++) {
            const ulonglong2 a01 = *(const ulonglong2*)&Asd[kk][ty * 16 + 0];
            const ulonglong2 a23 = *(const ulonglong2*)&Asd[kk][ty * 16 + 4];
            const ulonglong2 a45 = *(const ulonglong2*)&Asd[kk][ty * 16 + 8];
            const ulonglong2 a67 = *(const ulonglong2*)&Asd[kk][ty * 16 + 12];
            const ulonglong2 b03 = *(const ulonglong2*)&Bs[kk][tx * 8 + 0];
            const ulonglong2 b47 = *(const ulonglong2*)&Bs[kk][tx * 8 + 4];
            const ull a[8] = {a01.x, a01.y, a23.x, a23.y, a45.x, a45.y, a67.x, a67.y};
            const ull b[4] = {b03.x, b03.y, b47.x, b47.y};
#pragma unroll
            for (int i = 0; i < 8; i++)
#pragma unroll
                for (int jp = 0; jp < 4; jp++) fma2(acc[i][jp], a[i], b[jp]);
        }
        __syncthreads();
    }

    // unpack accumulators
    float accf[8][8];
#pragma unroll
    for (int i = 0; i < 8; i++)
#pragma unroll
        for (int jp = 0; jp < 4; jp++) {
            const float2 t = up2(acc[i][jp]);
            accf[i][2 * jp] = t.x; accf[i][2 * jp + 1] = t.y;
        }

    if (modeK) {
        float sr[8], sc[8];
#pragma unroll
        for (int i = 0; i < 8; i++) sr[i] = d_sq[r0 + ty * 8 + i];
#pragma unroll
        for (int j = 0; j < 8; j++) sc[j] = d_sq[c0 + tx * 8 + j];
#pragma unroll
        for (int i = 0; i < 8; i++)
#pragma unroll
            for (int j = 0; j < 8; j++) {
                const float c = fmaxf(sr[i] + sc[j] - 2.0f * accf[i][j], 0.0f);
                accf[i][j] = __expf(-ALPHA * c);
            }
        union { __half h[8]; uint4 u; } pk;
        // normal store (fp16)
#pragma unroll
        for (int i = 0; i < 8; i++) {
#pragma unroll
            for (int j = 0; j < 8; j++) pk.h[j] = __float2half_rn(accf[i][j]);
            *(uint4*)(d_Kh + (size_t)(r0 + ty * 8 + i) * D + c0 + tx * 8) = pk.u;
        }
        // mirror store
#pragma unroll
        for (int j = 0; j < 8; j++) {
#pragma unroll
            for (int i = 0; i < 8; i++) pk.h[i] = __float2half_rn(accf[i][j]);
            *(uint4*)(d_Kh + (size_t)(c0 + tx * 8 + j) * D + r0 + ty * 8) = pk.u;
        }
    } else {
#pragma unroll
        for (int i = 0; i < 8; i++) {
            float* p = d_G + (size_t)(r0 + ty * 8 + i) * D + c0 + tx * 8;
            *(float4*)(p)     = make_float4(accf[i][0], accf[i][1], accf[i][2], accf[i][3]);
            *(float4*)(p + 4) = make_float4(accf[i][4], accf[i][5], accf[i][6], accf[i][7]);
        }
#pragma unroll
        for (int j = 0; j < 8; j++) {
            float* p = d_G + (size_t)(c0 + tx * 8 + j) * D + r0 + ty * 8;
            *(float4*)(p)     = make_float4(accf[0][j], accf[1][j], accf[2][j], accf[3][j]);
            *(float4*)(p + 4) = make_float4(accf[4][j], accf[5][j], accf[6][j], accf[7][j]);
        }
    }
}

// ---------------- rowsum of Ghat -> invr ----------------
__global__ void __launch_bounds__(256) rowsum() {
    const int row  = blockIdx.x * 8 + (threadIdx.x >> 5);
    const int lane = threadIdx.x & 31;
    const float4* g = (const float4*)(d_G + (size_t)row * D);
    float s = 0.f;
#pragma unroll
    for (int it = 0; it < D / 128; it++) {
        const float4 v = g[lane + 32 * it];
        s += (v.x + v.y) + (v.z + v.w);
    }
    s = warp_red(s);
    if (lane == 0) d_invr[row] = 1.0f / s;
}

// two interleaved fp16 row-dots against smem fp32 vector, f32x2 accumulation
__device__ __forceinline__ void row_dot2h(const __half* __restrict__ K0,
                                          const __half* __restrict__ K1,
                                          const float* sx, int lane,
                                          float& o0, float& o1) {
    const uint4* a = (const uint4*)K0;   // 8 halves per uint4, 256 per row
    const uint4* b = (const uint4*)K1;
    ull s0a = 0ULL, s0b = 0ULL, s1a = 0ULL, s1b = 0ULL;
#pragma unroll
    for (int it = 0; it < 8; it++) {
        const int o = lane + 32 * it;
        const uint4 k0 = __ldg(a + o);
        const uint4 k1 = __ldg(b + o);
        const ulonglong2 x01 = *(const ulonglong2*)(sx + o * 8);
        const ulonglong2 x23 = *(const ulonglong2*)(sx + o * 8 + 4);
        fma2(s0a, h2f2(k0.x), x01.x); fma2(s0b, h2f2(k0.y), x01.y);
        fma2(s0a, h2f2(k0.z), x23.x); fma2(s0b, h2f2(k0.w), x23.y);
        fma2(s1a, h2f2(k1.x), x01.x); fma2(s1b, h2f2(k1.y), x01.y);
        fma2(s1a, h2f2(k1.z), x23.x); fma2(s1b, h2f2(k1.w), x23.y);
    }
    const float2 p0 = up2(s0a), q0 = up2(s0b);
    const float2 p1 = up2(s1a), q1 = up2(s1b);
    o0 = warp_red((p0.x + p0.y) + (q0.x + q0.y));
    o1 = warp_red((p1.x + p1.y) + (q1.x + q1.y));
}

// ---------------- persistent Sinkhorn (K symmetric => K^T u == K u) -------------
__global__ void __launch_bounds__(NT, 1) sinkhorn_kernel() {
    __shared__ float sx[D];
    __shared__ float sred[RPB];
    const int tid = threadIdx.x, bid = blockIdx.x;
    const int wid = tid >> 5, lane = tid & 31;
    const int row0 = bid * RPB + wid * 2;
    const float AB = 1.0f / (float)D;

    if (tid < RPB) { d_u[bid * RPB + tid] = 1.0f; d_v[bid * RPB + tid] = 1.0f; }

    unsigned ep = 1;
    gbar(ep, tid, bid); ep++;

    float err = 1.0f;
    int cpt = 0;
    while (err > STOPTHR && cpt < MAXIT) {
        // v = b / (K u + eps)
        for (int i = tid; i < D / 4; i += NT)
            ((float4*)sx)[i] = __ldcg(((const float4*)d_u) + i);
        __syncthreads();
        {
            float s0, s1;
            row_dot2h(d_Kh + (size_t)row0 * D, d_Kh + (size_t)(row0 + 1) * D, sx, lane, s0, s1);
            if (lane == 0) {
                d_v[row0]     = AB / (s0 + EPSF);
                d_v[row0 + 1] = AB / (s1 + EPSF);
            }
        }
        gbar(ep, tid, bid); ep++;

        // u = a / (K v + eps)
        for (int i = tid; i < D / 4; i += NT)
            ((float4*)sx)[i] = __ldcg(((const float4*)d_v) + i);
        __syncthreads();
        {
            float s0, s1;
            row_dot2h(d_Kh + (size_t)row0 * D, d_Kh + (size_t)(row0 + 1) * D, sx, lane, s0, s1);
            if (lane == 0) {
                d_u[row0]     = AB / (s0 + EPSF);
                d_u[row0 + 1] = AB / (s1 + EPSF);
            }
        }
        gbar(ep, tid, bid); ep++;

        cpt++;
        if (cpt % 50 == 1) {
            for (int i = tid; i < D / 4; i += NT)
                ((float4*)sx)[i] = __ldcg(((const float4*)d_u) + i);
            __syncthreads();
            {
                float s0, s1;
                row_dot2h(d_Kh + (size_t)row0 * D, d_Kh + (size_t)(row0 + 1) * D, sx, lane, s0, s1);
                if (lane == 0) {
                    sred[wid * 2]     = fabsf(__ldcg(&d_v[row0])     * s0 - AB);
                    sred[wid * 2 + 1] = fabsf(__ldcg(&d_v[row0 + 1]) * s1 - AB);
                }
            }
            __syncthreads();
            const int chk = cpt / 50;
            if (tid == 0) {
                float e = 0.f;
#pragma unroll
                for (int i = 0; i < RPB; i++) e += sred[i];
                d_errpart[chk * NB + bid] = e;
            }
            gbar(ep, tid, bid); ep++;
            float e = 0.f;
            for (int i = 0; i < NB; i++) e += __ldcg(&d_errpart[chk * NB + i]);
            err = e;
        }
    }
}

// ---------------- KL reduction ----------------
// Qt_ij = max(u_i K_ij v_j, 1e-6), S = sum Qt, P_ij = G_ij*(invr_i+invr_j)/2
// kl = sum P*log(P/Qt) + log(S) * sum P
__global__ void __launch_bounds__(NT) kl_partial() {
    const int tid = threadIdx.x;
    constexpr int TOT8 = D * D / 8;          // groups of 8 elements
    const int stride = NKB * NT;
    const uint4*  Kv = (const uint4*)d_Kh;   // 8 halves
    const float4* Gv = (const float4*)d_G;
    const float4* Vv = (const float4*)d_v;
    const float4* Rv = (const float4*)d_invr;

    float sS = 0.f, sP = 0.f, sK = 0.f;
    for (int g8 = blockIdx.x * NT + tid; g8 < TOT8; g8 += stride) {
        const int i  = g8 >> 8;              // 256 uint4 per row
        const int c8 = g8 & 255;
        const uint4 kh = Kv[g8];
        const float4 g0 = Gv[g8 * 2];
        const float4 g1 = Gv[g8 * 2 + 1];
        const float4 v0 = Vv[c8 * 2];
        const float4 v1 = Vv[c8 * 2 + 1];
        const float4 r0 = Rv[c8 * 2];
        const float4 r1 = Rv[c8 * 2 + 1];
        const float ui  = d_u[i];
        const float iri = d_invr[i];

        const float2 ka = __half22float2(*(const __half2*)&kh.x);
        const float2 kb = __half22float2(*(const __half2*)&kh.y);
        const float2 kc = __half22float2(*(const __half2*)&kh.z);
        const float2 kd = __half22float2(*(const __half2*)&kh.w);

        float q, p;
        q = fmaxf(ui * ka.x * v0.x, 1e-6f); p = g0.x * (0.5f * (iri + r0.x));
        sS += q; sP += p; sK += p * __logf(__fdividef(p, q));
        q = fmaxf(ui * ka.y * v0.y, 1e-6f); p = g0.y * (0.5f * (iri + r0.y));
        sS += q; sP += p; sK += p * __logf(__fdividef(p, q));
        q = fmaxf(ui * kb.x * v0.z, 1e-6f); p = g0.z * (0.5f * (iri + r0.z));
        sS += q; sP += p; sK += p * __logf(__fdividef(p, q));
        q = fmaxf(ui * kb.y * v0.w, 1e-6f); p = g0.w * (0.5f * (iri + r0.w));
        sS += q; sP += p; sK += p * __logf(__fdividef(p, q));
        q = fmaxf(ui * kc.x * v1.x, 1e-6f); p = g1.x * (0.5f * (iri + r1.x));
        sS += q; sP += p; sK += p * __logf(__fdividef(p, q));
        q = fmaxf(ui * kc.y * v1.y, 1e-6f); p = g1.y * (0.5f * (iri + r1.y));
        sS += q; sP += p; sK += p * __logf(__fdividef(p, q));
        q = fmaxf(ui * kd.x * v1.z, 1e-6f); p = g1.z * (0.5f * (iri + r1.z));
        sS += q; sP += p; sK += p * __logf(__fdividef(p, q));
        q = fmaxf(ui * kd.y * v1.w, 1e-6f); p = g1.w * (0.5f * (iri + r1.w));
        sS += q; sP += p; sK += p * __logf(__fdividef(p, q));
    }

    __shared__ double sd[NT];
    const double vals[3] = {(double)sS, (double)sP, (double)sK};
#pragma unroll
    for (int t = 0; t < 3; t++) {
        sd[tid] = vals[t];
        __syncthreads();
        for (int o = NT / 2; o; o >>= 1) {
            if (tid < o) sd[tid] += sd[tid + o];
            __syncthreads();
        }
        if (tid == 0) d_part[t * NKB + blockIdx.x] = sd[0];
        __syncthreads();
    }
}

__global__ void __launch_bounds__(NKB) finalize(float* out) {
    __shared__ double sd[NKB];
    const int tid = threadIdx.x;
    double acc[3];
#pragma unroll
    for (int t = 0; t < 3; t++) {
        sd[tid] = d_part[t * NKB + tid];
        __syncthreads();
        for (int o = NKB / 2; o; o >>= 1) {
            if (tid < o) sd[tid] += sd[tid + o];
            __syncthreads();
        }
        acc[t] = sd[0];
        __syncthreads();
    }
    if (tid == 0) out[0] = (float)(acc[2] + log(acc[0]) * acc[1]);
}

// ---------------- launch ----------------
extern "C" void kernel_launch(void* const* d_in, const int* in_sizes, int n_in,
                              void* d_out, int out_size) {
    const float* theta = (const float*)d_in[0];
    const float* emb   = (const float*)d_in[1];
    float* out = (float*)d_out;

    prep<<<D, F>>>(theta, emb);
    gemm_sym<<<2 * NBLK, 256>>>(theta);
    rowsum<<<D / 8, 256>>>();
    sinkhorn_kernel<<<NB, NT>>>();
    kl_partial<<<NKB, NT>>>();
    finalize<<<1, NKB>>>(out);
}

// round 8
// speedup vs baseline: 1.1804x; 1.1804x over previous
#include <cuda_runtime.h>
#include <cuda_fp16.h>
#include <cstdint>
#include <math.h>

// Problem constants
constexpr int   D       = 2048;
constexpr int   F       = 256;
constexpr float ALPHA   = 0.005f;   // SINKHORN_ALPHA
constexpr float STOPTHR = 0.005f;
constexpr float EPSF    = 1e-16f;
constexpr int   MAXIT   = 500;

// Launch shapes
constexpr int NB   = 128;         // persistent sinkhorn blocks
constexpr int NT   = 256;
constexpr int RPB  = D / NB;      // 16 rows per block
constexpr int NKB  = 256;
constexpr int NBLK = 136;         // triangular 128x128 tile count: 16*17/2

typedef unsigned long long ull;

// ---------------- device scratch ----------------
__device__ __half d_Kh[(size_t)D * D];    // 8 MB: K = exp(-alpha*C), fp16, symmetric
__device__ float  d_G[(size_t)D * D];     // 16 MB: Ghat = ehat ehat^T, symmetric
__device__ float  d_ehat[D * F];
__device__ float  d_sq[D];
__device__ float  d_invr[D];
__device__ float  d_u[D];
__device__ float  d_v[D];
__device__ float  d_errpart[12 * NB];
__device__ float  d_errglob[12];          // broadcast err per check (uniform exit)
__device__ double d_part[3 * NKB];
__device__ unsigned d_flags[NB];

// ---------------- f32x2 helpers (used in sinkhorn dot) ----------------
__device__ __forceinline__ ull pk2(float lo, float hi) {
    ull r; asm("mov.b64 %0,{%1,%2};" : "=l"(r) : "f"(lo), "f"(hi)); return r;
}
__device__ __forceinline__ float2 up2(ull v) {
    float2 f; asm("mov.b64 {%0,%1},%2;" : "=f"(f.x), "=f"(f.y) : "l"(v)); return f;
}
__device__ __forceinline__ void fma2(ull& d, ull a, ull b) {
    asm("fma.rn.f32x2 %0,%1,%2,%0;" : "+l"(d) : "l"(a), "l"(b));
}
__device__ __forceinline__ ull h2f2(unsigned h) {
    const float2 f = __half22float2(*reinterpret_cast<const __half2*>(&h));
    return pk2(f.x, f.y);
}

__device__ __forceinline__ float warp_red(float s) {
#pragma unroll
    for (int o = 16; o; o >>= 1) s += __shfl_xor_sync(0xffffffffu, s, o);
    return s;
}

// Forced-reload L2 poll: asm volatile + "memory" clobber — never hoisted.
__device__ __forceinline__ unsigned poll_flag(const unsigned* p) {
    unsigned v;
    asm volatile("ld.global.cg.u32 %0, [%1];" : "=r"(v) : "l"(p) : "memory");
    return v;
}

// Distributed flag grid barrier with CORRECT release semantics:
//   - EVERY thread fences its own prior global stores (threadfence is
//     per-thread; fencing only in tid 0 left peer lanes' data stores
//     unordered w.r.t. the flag -> stale reads -> divergent exits ->
//     deadlock, which is what hung rounds 6/7),
//   - __syncthreads so all fences complete before the flag is published,
//   - asm-volatile poll (no hoist), bounded spin with nanosleep fallback
//     after 4096 passes as a termination safety valve.
__device__ __forceinline__ void gbar(unsigned ep, int tid, int bid) {
    __threadfence();          // each thread: its stores visible at GPU scope
    __syncthreads();          // all fences done before the signal
    if (tid == 0) __stcg(&d_flags[bid], ep);
    if (tid < 32) {
        int spins = 0;
        for (;;) {
            int ok = 1;
#pragma unroll
            for (int k = 0; k < NB / 32; k++)
                if (poll_flag(&d_flags[tid * (NB / 32) + k]) < ep) ok = 0;
            if (__all_sync(0xffffffffu, ok)) break;
            if (++spins > 4096) __nanosleep(64);   // safety fallback
        }
        __threadfence();
    }
    __syncthreads();
}

// ---------------- prep: sq, ehat, flag reset ----------------
__global__ void __launch_bounds__(F) prep(const float* __restrict__ theta,
                                          const float* __restrict__ emb) {
    const int row = blockIdx.x, tid = threadIdx.x;
    if (tid == 0 && row < NB) d_flags[row] = 0u;

    const float t = theta[row * F + tid];
    const float e = emb[row * F + tid];
    float a = t * t, b = e * e;
#pragma unroll
    for (int o = 16; o; o >>= 1) {
        a += __shfl_xor_sync(0xffffffffu, a, o);
        b += __shfl_xor_sync(0xffffffffu, b, o);
    }
    __shared__ float sa[8], sb[8];
    __shared__ float s_inv;
    const int wid = tid >> 5, lane = tid & 31;
    if (lane == 0) { sa[wid] = a; sb[wid] = b; }
    __syncthreads();
    if (tid == 0) {
        float ta = 0.f, tb = 0.f;
#pragma unroll
        for (int i = 0; i < 8; i++) { ta += sa[i]; tb += sb[i]; }
        d_sq[row] = ta;
        s_inv = 1.0f / sqrtf(tb);
    }
    __syncthreads();
    d_ehat[row * F + tid] = e * s_inv;
}

// ---------------- symmetric fused GEMM (proven R4 FFMA microkernel) --------------
// bid in [0, NBLK)      : K (fp16 out) = exp(-alpha*max(sq_i+sq_j-2*theta theta^T,0))
// bid in [NBLK, 2*NBLK) : Ghat (fp32 out) = ehat ehat^T
// 128x128 tile, 8x8 per thread, lower-triangle blocks, mirror store.
__global__ void __launch_bounds__(256, 2) gemm_sym(const float* __restrict__ theta) {
    const int bid = blockIdx.x;
    const bool modeK = (bid < NBLK);
    const int tb = modeK ? bid : bid - NBLK;
    const float* __restrict__ X = modeK ? theta : (const float*)d_ehat;

    // triangular index -> (ib, jb), ib >= jb
    int ib = (int)((sqrtf(8.0f * (float)tb + 1.0f) - 1.0f) * 0.5f);
    while ((ib + 1) * (ib + 2) / 2 <= tb) ib++;
    while (ib * (ib + 1) / 2 > tb) ib--;
    const int jb = tb - ib * (ib + 1) / 2;

    __shared__ float As[16][128];
    __shared__ float Bs[16][128];
    const int tid = threadIdx.x;
    const int tx = tid & 15, ty = tid >> 4;
    const int r0 = ib * 128, c0 = jb * 128;

    float acc[8][8];
#pragma unroll
    for (int i = 0; i < 8; i++)
#pragma unroll
        for (int j = 0; j < 8; j++) acc[i][j] = 0.0f;

    for (int k0 = 0; k0 < F; k0 += 16) {
#pragma unroll
        for (int q = 0; q < 2; q++) {
            const int idx = tid * 2 + q;        // 0..511
            const int row = idx >> 2;           // 0..127
            const int kk  = (idx & 3) * 4;      // 0,4,8,12
            const float4 av = *(const float4*)(X + (size_t)(r0 + row) * F + k0 + kk);
            As[kk + 0][row] = av.x; As[kk + 1][row] = av.y;
            As[kk + 2][row] = av.z; As[kk + 3][row] = av.w;
            const float4 bv = *(const float4*)(X + (size_t)(c0 + row) * F + k0 + kk);
            Bs[kk + 0][row] = bv.x; Bs[kk + 1][row] = bv.y;
            Bs[kk + 2][row] = bv.z; Bs[kk + 3][row] = bv.w;
        }
        __syncthreads();
#pragma unroll
        for (int kk = 0; kk < 16; kk++) {
            float a[8], b[8];
#pragma unroll
            for (int i = 0; i < 8; i++) a[i] = As[kk][ty * 8 + i];
#pragma unroll
            for (int j = 0; j < 8; j++) b[j] = Bs[kk][tx * 8 + j];
#pragma unroll
            for (int i = 0; i < 8; i++)
#pragma unroll
                for (int j = 0; j < 8; j++) acc[i][j] = fmaf(a[i], b[j], acc[i][j]);
        }
        __syncthreads();
    }

    if (modeK) {
        float sr[8], sc[8];
#pragma unroll
        for (int i = 0; i < 8; i++) sr[i] = d_sq[r0 + ty * 8 + i];
#pragma unroll
        for (int j = 0; j < 8; j++) sc[j] = d_sq[c0 + tx * 8 + j];
#pragma unroll
        for (int i = 0; i < 8; i++)
#pragma unroll
            for (int j = 0; j < 8; j++) {
                const float c = fmaxf(sr[i] + sc[j] - 2.0f * acc[i][j], 0.0f);
                acc[i][j] = __expf(-ALPHA * c);
            }
        union { __half h[8]; uint4 u; } pk;
        // normal store (fp16)
#pragma unroll
        for (int i = 0; i < 8; i++) {
#pragma unroll
            for (int j = 0; j < 8; j++) pk.h[j] = __float2half_rn(acc[i][j]);
            *(uint4*)(d_Kh + (size_t)(r0 + ty * 8 + i) * D + c0 + tx * 8) = pk.u;
        }
        // mirror store (identical values on diagonal blocks)
#pragma unroll
        for (int j = 0; j < 8; j++) {
#pragma unroll
            for (int i = 0; i < 8; i++) pk.h[i] = __float2half_rn(acc[i][j]);
            *(uint4*)(d_Kh + (size_t)(c0 + tx * 8 + j) * D + r0 + ty * 8) = pk.u;
        }
    } else {
#pragma unroll
        for (int i = 0; i < 8; i++) {
            float* p = d_G + (size_t)(r0 + ty * 8 + i) * D + c0 + tx * 8;
            *(float4*)(p)     = make_float4(acc[i][0], acc[i][1], acc[i][2], acc[i][3]);
            *(float4*)(p + 4) = make_float4(acc[i][4], acc[i][5], acc[i][6], acc[i][7]);
        }
#pragma unroll
        for (int j = 0; j < 8; j++) {
            float* p = d_G + (size_t)(c0 + tx * 8 + j) * D + r0 + ty * 8;
            *(float4*)(p)     = make_float4(acc[0][j], acc[1][j], acc[2][j], acc[3][j]);
            *(float4*)(p + 4) = make_float4(acc[4][j], acc[5][j], acc[6][j], acc[7][j]);
        }
    }
}

// ---------------- rowsum of Ghat -> invr ----------------
__global__ void __launch_bounds__(256) rowsum() {
    const int row  = blockIdx.x * 8 + (threadIdx.x >> 5);
    const int lane = threadIdx.x & 31;
    const float4* g = (const float4*)(d_G + (size_t)row * D);
    float s = 0.f;
#pragma unroll
    for (int it = 0; it < D / 128; it++) {
        const float4 v = g[lane + 32 * it];
        s += (v.x + v.y) + (v.z + v.w);
    }
    s = warp_red(s);
    if (lane == 0) d_invr[row] = 1.0f / s;
}

// two interleaved fp16 row-dots against smem fp32 vector, f32x2 accumulation
__device__ __forceinline__ void row_dot2h(const __half* __restrict__ K0,
                                          const __half* __restrict__ K1,
                                          const float* sx, int lane,
                                          float& o0, float& o1) {
    const uint4* a = (const uint4*)K0;   // 8 halves per uint4, 256 per row
    const uint4* b = (const uint4*)K1;
    ull s0a = 0ULL, s0b = 0ULL, s1a = 0ULL, s1b = 0ULL;
#pragma unroll
    for (int it = 0; it < 8; it++) {
        const int o = lane + 32 * it;
        const uint4 k0 = __ldg(a + o);
        const uint4 k1 = __ldg(b + o);
        const ulonglong2 x01 = *(const ulonglong2*)(sx + o * 8);
        const ulonglong2 x23 = *(const ulonglong2*)(sx + o * 8 + 4);
        fma2(s0a, h2f2(k0.x), x01.x); fma2(s0b, h2f2(k0.y), x01.y);
        fma2(s0a, h2f2(k0.z), x23.x); fma2(s0b, h2f2(k0.w), x23.y);
        fma2(s1a, h2f2(k1.x), x01.x); fma2(s1b, h2f2(k1.y), x01.y);
        fma2(s1a, h2f2(k1.z), x23.x); fma2(s1b, h2f2(k1.w), x23.y);
    }
    const float2 p0 = up2(s0a), q0 = up2(s0b);
    const float2 p1 = up2(s1a), q1 = up2(s1b);
    o0 = warp_red((p0.x + p0.y) + (q0.x + q0.y));
    o1 = warp_red((p1.x + p1.y) + (q1.x + q1.y));
}

// ---------------- persistent Sinkhorn (K symmetric => K^T u == K u) -------------
__global__ void __launch_bounds__(NT, 1) sinkhorn_kernel() {
    __shared__ float sx[D];
    __shared__ float sred[RPB];
    const int tid = threadIdx.x, bid = blockIdx.x;
    const int wid = tid >> 5, lane = tid & 31;
    const int row0 = bid * RPB + wid * 2;
    const float AB = 1.0f / (float)D;

    if (tid < RPB) { d_u[bid * RPB + tid] = 1.0f; d_v[bid * RPB + tid] = 1.0f; }

    unsigned ep = 1;
    gbar(ep, tid, bid); ep++;

    float err = 1.0f;
    int cpt = 0;
    while (err > STOPTHR && cpt < MAXIT) {
        // v = b / (K u + eps)
        for (int i = tid; i < D / 4; i += NT)
            ((float4*)sx)[i] = __ldcg(((const float4*)d_u) + i);
        __syncthreads();
        {
            float s0, s1;
            row_dot2h(d_Kh + (size_t)row0 * D, d_Kh + (size_t)(row0 + 1) * D, sx, lane, s0, s1);
            if (lane == 0) {
                d_v[row0]     = AB / (s0 + EPSF);
                d_v[row0 + 1] = AB / (s1 + EPSF);
            }
        }
        gbar(ep, tid, bid); ep++;

        // u = a / (K v + eps)
        for (int i = tid; i < D / 4; i += NT)
            ((float4*)sx)[i] = __ldcg(((const float4*)d_v) + i);
        __syncthreads();
        {
            float s0, s1;
            row_dot2h(d_Kh + (size_t)row0 * D, d_Kh + (size_t)(row0 + 1) * D, sx, lane, s0, s1);
            if (lane == 0) {
                d_u[row0]     = AB / (s0 + EPSF);
                d_u[row0 + 1] = AB / (s1 + EPSF);
            }
        }
        gbar(ep, tid, bid); ep++;

        cpt++;
        if (cpt % 50 == 1) {
            // err = sum_i | v_i * (K u_new)_i - b |
            for (int i = tid; i < D / 4; i += NT)
                ((float4*)sx)[i] = __ldcg(((const float4*)d_u) + i);
            __syncthreads();
            {
                float s0, s1;
                row_dot2h(d_Kh + (size_t)row0 * D, d_Kh + (size_t)(row0 + 1) * D, sx, lane, s0, s1);
                if (lane == 0) {
                    sred[wid * 2]     = fabsf(__ldcg(&d_v[row0])     * s0 - AB);
                    sred[wid * 2 + 1] = fabsf(__ldcg(&d_v[row0 + 1]) * s1 - AB);
                }
            }
            __syncthreads();
            const int chk = cpt / 50;
            if (tid == 0) {
                float e = 0.f;
#pragma unroll
                for (int i = 0; i < RPB; i++) e += sred[i];
                d_errpart[chk * NB + bid] = e;
            }
            gbar(ep, tid, bid); ep++;
            // block 0 reduces and BROADCASTS one float: all blocks branch on
            // the identical loaded word -> uniform exit by construction.
            if (bid == 0 && tid == 0) {
                float e = 0.f;
                for (int i = 0; i < NB; i++) e += __ldcg(&d_errpart[chk * NB + i]);
                d_errglob[chk] = e;
            }
            gbar(ep, tid, bid); ep++;
            err = __ldcg(&d_errglob[chk]);
        }
    }
}

// ---------------- KL reduction ----------------
// Qt_ij = max(u_i K_ij v_j, 1e-6), S = sum Qt, P_ij = G_ij*(invr_i+invr_j)/2
// kl = sum P*log(P/Qt) + log(S) * sum P
__global__ void __launch_bounds__(NT) kl_partial() {
    const int tid = threadIdx.x;
    constexpr int TOT8 = D * D / 8;
    const int stride = NKB * NT;
    const uint4*  Kv = (const uint4*)d_Kh;
    const float4* Gv = (const float4*)d_G;
    const float4* Vv = (const float4*)d_v;
    const float4* Rv = (const float4*)d_invr;

    float sS = 0.f, sP = 0.f, sK = 0.f;
    for (int g8 = blockIdx.x * NT + tid; g8 < TOT8; g8 += stride) {
        const int i  = g8 >> 8;
        const int c8 = g8 & 255;
        const uint4 kh = Kv[g8];
        const float4 g0 = Gv[g8 * 2];
        const float4 g1 = Gv[g8 * 2 + 1];
        const float4 v0 = Vv[c8 * 2];
        const float4 v1 = Vv[c8 * 2 + 1];
        const float4 r0 = Rv[c8 * 2];
        const float4 r1 = Rv[c8 * 2 + 1];
        const float ui  = d_u[i];
        const float iri = d_invr[i];

        const float2 ka = __half22float2(*(const __half2*)&kh.x);
        const float2 kb = __half22float2(*(const __half2*)&kh.y);
        const float2 kc = __half22float2(*(const __half2*)&kh.z);
        const float2 kd = __half22float2(*(const __half2*)&kh.w);

        float q, p;
        q = fmaxf(ui * ka.x * v0.x, 1e-6f); p = g0.x * (0.5f * (iri + r0.x));
        sS += q; sP += p; sK += p * __logf(__fdividef(p, q));
        q = fmaxf(ui * ka.y * v0.y, 1e-6f); p = g0.y * (0.5f * (iri + r0.y));
        sS += q; sP += p; sK += p * __logf(__fdividef(p, q));
        q = fmaxf(ui * kb.x * v0.z, 1e-6f); p = g0.z * (0.5f * (iri + r0.z));
        sS += q; sP += p; sK += p * __logf(__fdividef(p, q));
        q = fmaxf(ui * kb.y * v0.w, 1e-6f); p = g0.w * (0.5f * (iri + r0.w));
        sS += q; sP += p; sK += p * __logf(__fdividef(p, q));
        q = fmaxf(ui * kc.x * v1.x, 1e-6f); p = g1.x * (0.5f * (iri + r1.x));
        sS += q; sP += p; sK += p * __logf(__fdividef(p, q));
        q = fmaxf(ui * kc.y * v1.y, 1e-6f); p = g1.y * (0.5f * (iri + r1.y));
        sS += q; sP += p; sK += p * __logf(__fdividef(p, q));
        q = fmaxf(ui * kd.x * v1.z, 1e-6f); p = g1.z * (0.5f * (iri + r1.z));
        sS += q; sP += p; sK += p * __logf(__fdividef(p, q));
        q = fmaxf(ui * kd.y * v1.w, 1e-6f); p = g1.w * (0.5f * (iri + r1.w));
        sS += q; sP += p; sK += p * __logf(__fdividef(p, q));
    }

    __shared__ double sd[NT];
    const double vals[3] = {(double)sS, (double)sP, (double)sK};
#pragma unroll
    for (int t = 0; t < 3; t++) {
        sd[tid] = vals[t];
        __syncthreads();
        for (int o = NT / 2; o; o >>= 1) {
            if (tid < o) sd[tid] += sd[tid + o];
            __syncthreads();
        }
        if (tid == 0) d_part[t * NKB + blockIdx.x] = sd[0];
        __syncthreads();
    }
}

__global__ void __launch_bounds__(NKB) finalize(float* out) {
    __shared__ double sd[NKB];
    const int tid = threadIdx.x;
    double acc[3];
#pragma unroll
    for (int t = 0; t < 3; t++) {
        sd[tid] = d_part[t * NKB + tid];
        __syncthreads();
        for (int o = NKB / 2; o; o >>= 1) {
            if (tid < o) sd[tid] += sd[tid + o];
            __syncthreads();
        }
        acc[t] = sd[0];
        __syncthreads();
    }
    if (tid == 0) out[0] = (float)(acc[2] + log(acc[0]) * acc[1]);
}

// ---------------- launch ----------------
extern "C" void kernel_launch(void* const* d_in, const int* in_sizes, int n_in,
                              void* d_out, int out_size) {
    const float* theta = (const float*)d_in[0];
    const float* emb   = (const float*)d_in[1];
    float* out = (float*)d_out;

    prep<<<D, F>>>(theta, emb);
    gemm_sym<<<2 * NBLK, 256>>>(theta);
    rowsum<<<D / 8, 256>>>();
    sinkhorn_kernel<<<NB, NT>>>();
    kl_partial<<<NKB, NT>>>();
    finalize<<<1, NKB>>>(out);
}

// round 9
// speedup vs baseline: 1.5593x; 1.3210x over previous
#include <cuda_runtime.h>
#include <cuda_fp16.h>
#include <cstdint>
#include <math.h>

// Problem constants
constexpr int   D       = 2048;
constexpr int   F       = 256;
constexpr float ALPHA   = 0.005f;   // SINKHORN_ALPHA
constexpr float STOPTHR = 0.005f;
constexpr float EPSF    = 1e-16f;
constexpr int   MAXIT   = 500;

// Launch shapes
constexpr int NB   = 128;         // persistent sinkhorn blocks
constexpr int NT   = 256;
constexpr int RPB  = D / NB;      // 16 rows per block
constexpr int NKB  = 256;
constexpr int NBLK = 136;         // triangular 128x128 tile count: 16*17/2

// GEMM smem: two 128x132 u32 tiles (tf32), epilogue reuses tile A as 128x132 f32
constexpr int PITCH = 132;
constexpr int TILEW = 128 * PITCH;            // words per tile
constexpr int GEMM_SMEM = 2 * TILEW * 4;      // 135168 bytes

typedef unsigned long long ull;

// ---------------- device scratch ----------------
__device__ __half d_Kh[(size_t)D * D];    // 8 MB: K = exp(-alpha*C), fp16, symmetric
__device__ float  d_G[(size_t)D * D];     // 16 MB: Ghat = ehat ehat^T, symmetric
__device__ float  d_ehat[D * F];
__device__ float  d_sq[D];
__device__ float  d_invr[D];
__device__ float  d_u[D];
__device__ float  d_v[D];
__device__ float  d_errpart[12 * NB];
__device__ float  d_errglob[12];          // broadcast err per check (uniform exit)
__device__ double d_part[3 * NKB];
__device__ unsigned d_flags[NB];

// ---------------- f32x2 helpers (used in sinkhorn dot) ----------------
__device__ __forceinline__ ull pk2(float lo, float hi) {
    ull r; asm("mov.b64 %0,{%1,%2};" : "=l"(r) : "f"(lo), "f"(hi)); return r;
}
__device__ __forceinline__ float2 up2(ull v) {
    float2 f; asm("mov.b64 {%0,%1},%2;" : "=f"(f.x), "=f"(f.y) : "l"(v)); return f;
}
__device__ __forceinline__ void fma2(ull& d, ull a, ull b) {
    asm("fma.rn.f32x2 %0,%1,%2,%0;" : "+l"(d) : "l"(a), "l"(b));
}
__device__ __forceinline__ ull h2f2(unsigned h) {
    const float2 f = __half22float2(*reinterpret_cast<const __half2*>(&h));
    return pk2(f.x, f.y);
}

// ---------------- tf32 mma helpers ----------------
__device__ __forceinline__ uint32_t f2tf32(float f) {
    uint32_t r; asm("cvt.rna.tf32.f32 %0,%1;" : "=r"(r) : "f"(f)); return r;
}
__device__ __forceinline__ void mma_tf32(float* c, const uint32_t* a, const uint32_t* b) {
    asm("mma.sync.aligned.m16n8k8.row.col.f32.tf32.tf32.f32 "
        "{%0,%1,%2,%3},{%4,%5,%6,%7},{%8,%9},{%0,%1,%2,%3};"
        : "+f"(c[0]), "+f"(c[1]), "+f"(c[2]), "+f"(c[3])
        : "r"(a[0]), "r"(a[1]), "r"(a[2]), "r"(a[3]), "r"(b[0]), "r"(b[1]));
}

__device__ __forceinline__ float warp_red(float s) {
#pragma unroll
    for (int o = 16; o; o >>= 1) s += __shfl_xor_sync(0xffffffffu, s, o);
    return s;
}

// Forced-reload L2 poll: asm volatile + "memory" clobber — never hoisted.
__device__ __forceinline__ unsigned poll_flag(const unsigned* p) {
    unsigned v;
    asm volatile("ld.global.cg.u32 %0, [%1];" : "=r"(v) : "l"(p) : "memory");
    return v;
}

// Distributed flag grid barrier with full release semantics (every thread
// fences its own stores before the block-wide sync; tid 0 then publishes).
__device__ __forceinline__ void gbar(unsigned ep, int tid, int bid) {
    __threadfence();
    __syncthreads();
    if (tid == 0) __stcg(&d_flags[bid], ep);
    if (tid < 32) {
        int spins = 0;
        for (;;) {
            int ok = 1;
#pragma unroll
            for (int k = 0; k < NB / 32; k++)
                if (poll_flag(&d_flags[tid * (NB / 32) + k]) < ep) ok = 0;
            if (__all_sync(0xffffffffu, ok)) break;
            if (++spins > 4096) __nanosleep(64);   // safety fallback
        }
        __threadfence();
    }
    __syncthreads();
}

// ---------------- prep: sq, ehat, flag reset ----------------
__global__ void __launch_bounds__(F) prep(const float* __restrict__ theta,
                                          const float* __restrict__ emb) {
    const int row = blockIdx.x, tid = threadIdx.x;
    if (tid == 0 && row < NB) d_flags[row] = 0u;

    const float t = theta[row * F + tid];
    const float e = emb[row * F + tid];
    float a = t * t, b = e * e;
#pragma unroll
    for (int o = 16; o; o >>= 1) {
        a += __shfl_xor_sync(0xffffffffu, a, o);
        b += __shfl_xor_sync(0xffffffffu, b, o);
    }
    __shared__ float sa[8], sb[8];
    __shared__ float s_inv;
    const int wid = tid >> 5, lane = tid & 31;
    if (lane == 0) { sa[wid] = a; sb[wid] = b; }
    __syncthreads();
    if (tid == 0) {
        float ta = 0.f, tb = 0.f;
#pragma unroll
        for (int i = 0; i < 8; i++) { ta += sa[i]; tb += sb[i]; }
        d_sq[row] = ta;
        s_inv = 1.0f / sqrtf(tb);
    }
    __syncthreads();
    d_ehat[row * F + tid] = e * s_inv;
}

// ---------------- symmetric fused GEMM — tf32 tensor cores --------------
// bid in [0, NBLK)      : K (fp16 out) = exp(-alpha*max(sq_i+sq_j-2*theta theta^T,0))
// bid in [NBLK, 2*NBLK) : Ghat (fp32 out) = ehat ehat^T
// 128x128 tile per block, 8 warps x (64x32) warp tiles of m16n8k8 tf32 mma.
// Lower-triangle blocks only; smem-transpose epilogue -> coalesced mirror store.
__global__ void __launch_bounds__(256, 1) gemm_sym(const float* __restrict__ theta) {
    extern __shared__ uint32_t smw[];
    uint32_t* As = smw;            // [128][PITCH] tf32
    uint32_t* Bs = smw + TILEW;    // [128][PITCH] tf32

    const int bid = blockIdx.x;
    const bool modeK = (bid < NBLK);
    const int tb = modeK ? bid : bid - NBLK;
    const float* __restrict__ X = modeK ? theta : (const float*)d_ehat;

    // triangular index -> (ib, jb), ib >= jb
    int ib = (int)((sqrtf(8.0f * (float)tb + 1.0f) - 1.0f) * 0.5f);
    while ((ib + 1) * (ib + 2) / 2 <= tb) ib++;
    while (ib * (ib + 1) / 2 > tb) ib--;
    const int jb = tb - ib * (ib + 1) / 2;
    const int r0 = ib * 128, c0 = jb * 128;

    const int tid  = threadIdx.x;
    const int wid  = tid >> 5, lane = tid & 31;
    const int g    = lane >> 2, t = lane & 3;   // fragment group / thread-in-group
    const int wm   = wid >> 2,  wn = wid & 3;   // warp tile: rows wm*64, cols wn*32

    float c[4][4][4];
#pragma unroll
    for (int am = 0; am < 4; am++)
#pragma unroll
        for (int bn = 0; bn < 4; bn++)
#pragma unroll
            for (int e = 0; e < 4; e++) c[am][bn][e] = 0.0f;

    for (int kc = 0; kc < 2; kc++) {           // two 128-wide K chunks
        // stage: fp32 -> tf32 into padded smem (k-contiguous rows)
        for (int idx = tid; idx < 128 * 32; idx += 256) {
            const int r = idx >> 5, q = (idx & 31) * 4;
            const float4 av = *(const float4*)(X + (size_t)(r0 + r) * F + kc * 128 + q);
            uint4 ua;
            ua.x = f2tf32(av.x); ua.y = f2tf32(av.y);
            ua.z = f2tf32(av.z); ua.w = f2tf32(av.w);
            *(uint4*)&As[r * PITCH + q] = ua;
            const float4 bv = *(const float4*)(X + (size_t)(c0 + r) * F + kc * 128 + q);
            uint4 ub;
            ub.x = f2tf32(bv.x); ub.y = f2tf32(bv.y);
            ub.z = f2tf32(bv.z); ub.w = f2tf32(bv.w);
            *(uint4*)&Bs[r * PITCH + q] = ub;
        }
        __syncthreads();

#pragma unroll 4
        for (int s = 0; s < 16; s++) {         // k-steps of 8
            uint32_t a[4][4], b[4][2];
#pragma unroll
            for (int am = 0; am < 4; am++) {
                const uint32_t* p = As + (wm * 64 + am * 16 + g) * PITCH + s * 8 + t;
                a[am][0] = p[0];
                a[am][1] = p[8 * PITCH];
                a[am][2] = p[4];
                a[am][3] = p[8 * PITCH + 4];
            }
#pragma unroll
            for (int bn = 0; bn < 4; bn++) {
                const uint32_t* p = Bs + (wn * 32 + bn * 8 + g) * PITCH + s * 8 + t;
                b[bn][0] = p[0];
                b[bn][1] = p[4];
            }
#pragma unroll
            for (int am = 0; am < 4; am++)
#pragma unroll
                for (int bn = 0; bn < 4; bn++)
                    mma_tf32(c[am][bn], a[am], b[bn]);
        }
        __syncthreads();                        // before next stage overwrites
    }

    // ---- epilogue: fragments -> smem (reuse As region), then coalesced stores
    float* Ct = (float*)smw;                    // [128][PITCH]
#pragma unroll
    for (int am = 0; am < 4; am++) {
        const int r = wm * 64 + am * 16 + g;
#pragma unroll
        for (int bn = 0; bn < 4; bn++) {
            const int cc = wn * 32 + bn * 8 + 2 * t;
            *(float2*)&Ct[r * PITCH + cc]       = make_float2(c[am][bn][0], c[am][bn][1]);
            *(float2*)&Ct[(r + 8) * PITCH + cc] = make_float2(c[am][bn][2], c[am][bn][3]);
        }
    }
    __syncthreads();

    if (modeK) {
        // normal rows (coalesced)
        for (int idx = tid; idx < 128 * 32; idx += 256) {
            const int r = idx >> 5, q = (idx & 31) * 4;
            const float4 cv = *(const float4*)&Ct[r * PITCH + q];
            const float sr = __ldg(&d_sq[r0 + r]);
            union { __half h[4]; uint2 u; } pk;
            pk.h[0] = __float2half_rn(__expf(-ALPHA * fmaxf(sr + __ldg(&d_sq[c0 + q + 0]) - 2.0f * cv.x, 0.0f)));
            pk.h[1] = __float2half_rn(__expf(-ALPHA * fmaxf(sr + __ldg(&d_sq[c0 + q + 1]) - 2.0f * cv.y, 0.0f)));
            pk.h[2] = __float2half_rn(__expf(-ALPHA * fmaxf(sr + __ldg(&d_sq[c0 + q + 2]) - 2.0f * cv.z, 0.0f)));
            pk.h[3] = __float2half_rn(__expf(-ALPHA * fmaxf(sr + __ldg(&d_sq[c0 + q + 3]) - 2.0f * cv.w, 0.0f)));
            *(uint2*)(d_Kh + (size_t)(r0 + r) * D + c0 + q) = pk.u;
        }
        // mirror rows: lanes along m -> conflict-free column reads of Ct
        for (int idx = tid; idx < 128 * 32; idx += 256) {
            const int m = idx & 127, q = (idx >> 7) * 4;
            const float sm = __ldg(&d_sq[c0 + m]);
            union { __half h[4]; uint2 u; } pk;
#pragma unroll
            for (int e = 0; e < 4; e++) {
                const float v = Ct[(q + e) * PITCH + m];
                pk.h[e] = __float2half_rn(__expf(-ALPHA * fmaxf(sm + __ldg(&d_sq[r0 + q + e]) - 2.0f * v, 0.0f)));
            }
            *(uint2*)(d_Kh + (size_t)(c0 + m) * D + r0 + q) = pk.u;
        }
    } else {
        for (int idx = tid; idx < 128 * 32; idx += 256) {
            const int r = idx >> 5, q = (idx & 31) * 4;
            *(float4*)(d_G + (size_t)(r0 + r) * D + c0 + q) = *(const float4*)&Ct[r * PITCH + q];
        }
        for (int idx = tid; idx < 128 * 32; idx += 256) {
            const int m = idx & 127, q = (idx >> 7) * 4;
            float4 v;
            v.x = Ct[(q + 0) * PITCH + m];
            v.y = Ct[(q + 1) * PITCH + m];
            v.z = Ct[(q + 2) * PITCH + m];
            v.w = Ct[(q + 3) * PITCH + m];
            *(float4*)(d_G + (size_t)(c0 + m) * D + r0 + q) = v;
        }
    }
}

// ---------------- rowsum of Ghat -> invr ----------------
__global__ void __launch_bounds__(256) rowsum() {
    const int row  = blockIdx.x * 8 + (threadIdx.x >> 5);
    const int lane = threadIdx.x & 31;
    const float4* g = (const float4*)(d_G + (size_t)row * D);
    float s = 0.f;
#pragma unroll
    for (int it = 0; it < D / 128; it++) {
        const float4 v = g[lane + 32 * it];
        s += (v.x + v.y) + (v.z + v.w);
    }
    s = warp_red(s);
    if (lane == 0) d_invr[row] = 1.0f / s;
}

// two interleaved fp16 row-dots against smem fp32 vector, f32x2 accumulation
__device__ __forceinline__ void row_dot2h(const __half* __restrict__ K0,
                                          const __half* __restrict__ K1,
                                          const float* sx, int lane,
                                          float& o0, float& o1) {
    const uint4* a = (const uint4*)K0;   // 8 halves per uint4, 256 per row
    const uint4* b = (const uint4*)K1;
    ull s0a = 0ULL, s0b = 0ULL, s1a = 0ULL, s1b = 0ULL;
#pragma unroll
    for (int it = 0; it < 8; it++) {
        const int o = lane + 32 * it;
        const uint4 k0 = __ldg(a + o);
        const uint4 k1 = __ldg(b + o);
        const ulonglong2 x01 = *(const ulonglong2*)(sx + o * 8);
        const ulonglong2 x23 = *(const ulonglong2*)(sx + o * 8 + 4);
        fma2(s0a, h2f2(k0.x), x01.x); fma2(s0b, h2f2(k0.y), x01.y);
        fma2(s0a, h2f2(k0.z), x23.x); fma2(s0b, h2f2(k0.w), x23.y);
        fma2(s1a, h2f2(k1.x), x01.x); fma2(s1b, h2f2(k1.y), x01.y);
        fma2(s1a, h2f2(k1.z), x23.x); fma2(s1b, h2f2(k1.w), x23.y);
    }
    const float2 p0 = up2(s0a), q0 = up2(s0b);
    const float2 p1 = up2(s1a), q1 = up2(s1b);
    o0 = warp_red((p0.x + p0.y) + (q0.x + q0.y));
    o1 = warp_red((p1.x + p1.y) + (q1.x + q1.y));
}

// ---------------- persistent Sinkhorn (K symmetric => K^T u == K u) -------------
__global__ void __launch_bounds__(NT, 1) sinkhorn_kernel() {
    __shared__ float sx[D];
    __shared__ float sred[RPB];
    const int tid = threadIdx.x, bid = blockIdx.x;
    const int wid = tid >> 5, lane = tid & 31;
    const int row0 = bid * RPB + wid * 2;
    const float AB = 1.0f / (float)D;

    if (tid < RPB) { d_u[bid * RPB + tid] = 1.0f; d_v[bid * RPB + tid] = 1.0f; }

    unsigned ep = 1;
    gbar(ep, tid, bid); ep++;

    float err = 1.0f;
    int cpt = 0;
    while (err > STOPTHR && cpt < MAXIT) {
        // v = b / (K u + eps)
        for (int i = tid; i < D / 4; i += NT)
            ((float4*)sx)[i] = __ldcg(((const float4*)d_u) + i);
        __syncthreads();
        {
            float s0, s1;
            row_dot2h(d_Kh + (size_t)row0 * D, d_Kh + (size_t)(row0 + 1) * D, sx, lane, s0, s1);
            if (lane == 0) {
                d_v[row0]     = AB / (s0 + EPSF);
                d_v[row0 + 1] = AB / (s1 + EPSF);
            }
        }
        gbar(ep, tid, bid); ep++;

        // u = a / (K v + eps)
        for (int i = tid; i < D / 4; i += NT)
            ((float4*)sx)[i] = __ldcg(((const float4*)d_v) + i);
        __syncthreads();
        {
            float s0, s1;
            row_dot2h(d_Kh + (size_t)row0 * D, d_Kh + (size_t)(row0 + 1) * D, sx, lane, s0, s1);
            if (lane == 0) {
                d_u[row0]     = AB / (s0 + EPSF);
                d_u[row0 + 1] = AB / (s1 + EPSF);
            }
        }
        gbar(ep, tid, bid); ep++;

        cpt++;
        if (cpt % 50 == 1) {
            // err = sum_i | v_i * (K u_new)_i - b |
            for (int i = tid; i < D / 4; i += NT)
                ((float4*)sx)[i] = __ldcg(((const float4*)d_u) + i);
            __syncthreads();
            {
                float s0, s1;
                row_dot2h(d_Kh + (size_t)row0 * D, d_Kh + (size_t)(row0 + 1) * D, sx, lane, s0, s1);
                if (lane == 0) {
                    sred[wid * 2]     = fabsf(__ldcg(&d_v[row0])     * s0 - AB);
                    sred[wid * 2 + 1] = fabsf(__ldcg(&d_v[row0 + 1]) * s1 - AB);
                }
            }
            __syncthreads();
            const int chk = cpt / 50;
            if (tid == 0) {
                float e = 0.f;
#pragma unroll
                for (int i = 0; i < RPB; i++) e += sred[i];
                d_errpart[chk * NB + bid] = e;
            }
            gbar(ep, tid, bid); ep++;
            // block 0 reduces and broadcasts one float: uniform exit.
            if (bid == 0 && tid == 0) {
                float e = 0.f;
                for (int i = 0; i < NB; i++) e += __ldcg(&d_errpart[chk * NB + i]);
                d_errglob[chk] = e;
            }
            gbar(ep, tid, bid); ep++;
            err = __ldcg(&d_errglob[chk]);
        }
    }
}

// ---------------- KL reduction ----------------
// Qt_ij = max(u_i K_ij v_j, 1e-6), S = sum Qt, P_ij = G_ij*(invr_i+invr_j)/2
// kl = sum P*log(P/Qt) + log(S) * sum P
__global__ void __launch_bounds__(NT) kl_partial() {
    const int tid = threadIdx.x;
    constexpr int TOT8 = D * D / 8;
    const int stride = NKB * NT;
    const uint4*  Kv = (const uint4*)d_Kh;
    const float4* Gv = (const float4*)d_G;
    const float4* Vv = (const float4*)d_v;
    const float4* Rv = (const float4*)d_invr;

    float sS = 0.f, sP = 0.f, sK = 0.f;
    for (int g8 = blockIdx.x * NT + tid; g8 < TOT8; g8 += stride) {
        const int i  = g8 >> 8;
        const int c8 = g8 & 255;
        const uint4 kh = Kv[g8];
        const float4 g0 = Gv[g8 * 2];
        const float4 g1 = Gv[g8 * 2 + 1];
        const float4 v0 = Vv[c8 * 2];
        const float4 v1 = Vv[c8 * 2 + 1];
        const float4 r0 = Rv[c8 * 2];
        const float4 r1 = Rv[c8 * 2 + 1];
        const float ui  = d_u[i];
        const float iri = d_invr[i];

        const float2 ka = __half22float2(*(const __half2*)&kh.x);
        const float2 kb = __half22float2(*(const __half2*)&kh.y);
        const float2 kc = __half22float2(*(const __half2*)&kh.z);
        const float2 kd = __half22float2(*(const __half2*)&kh.w);

        float q, p;
        q = fmaxf(ui * ka.x * v0.x, 1e-6f); p = g0.x * (0.5f * (iri + r0.x));
        sS += q; sP += p; sK += p * __logf(__fdividef(p, q));
        q = fmaxf(ui * ka.y * v0.y, 1e-6f); p = g0.y * (0.5f * (iri + r0.y));
        sS += q; sP += p; sK += p * __logf(__fdividef(p, q));
        q = fmaxf(ui * kb.x * v0.z, 1e-6f); p = g0.z * (0.5f * (iri + r0.z));
        sS += q; sP += p; sK += p * __logf(__fdividef(p, q));
        q = fmaxf(ui * kb.y * v0.w, 1e-6f); p = g0.w * (0.5f * (iri + r0.w));
        sS += q; sP += p; sK += p * __logf(__fdividef(p, q));
        q = fmaxf(ui * kc.x * v1.x, 1e-6f); p = g1.x * (0.5f * (iri + r1.x));
        sS += q; sP += p; sK += p * __logf(__fdividef(p, q));
        q = fmaxf(ui * kc.y * v1.y, 1e-6f); p = g1.y * (0.5f * (iri + r1.y));
        sS += q; sP += p; sK += p * __logf(__fdividef(p, q));
        q = fmaxf(ui * kd.x * v1.z, 1e-6f); p = g1.z * (0.5f * (iri + r1.z));
        sS += q; sP += p; sK += p * __logf(__fdividef(p, q));
        q = fmaxf(ui * kd.y * v1.w, 1e-6f); p = g1.w * (0.5f * (iri + r1.w));
        sS += q; sP += p; sK += p * __logf(__fdividef(p, q));
    }

    __shared__ double sd[NT];
    const double vals[3] = {(double)sS, (double)sP, (double)sK};
#pragma unroll
    for (int t = 0; t < 3; t++) {
        sd[tid] = vals[t];
        __syncthreads();
        for (int o = NT / 2; o; o >>= 1) {
            if (tid < o) sd[tid] += sd[tid + o];
            __syncthreads();
        }
        if (tid == 0) d_part[t * NKB + blockIdx.x] = sd[0];
        __syncthreads();
    }
}

__global__ void __launch_bounds__(NKB) finalize(float* out) {
    __shared__ double sd[NKB];
    const int tid = threadIdx.x;
    double acc[3];
#pragma unroll
    for (int t = 0; t < 3; t++) {
        sd[tid] = d_part[t * NKB + tid];
        __syncthreads();
        for (int o = NKB / 2; o; o >>= 1) {
            if (tid < o) sd[tid] += sd[tid + o];
            __syncthreads();
        }
        acc[t] = sd[0];
        __syncthreads();
    }
    if (tid == 0) out[0] = (float)(acc[2] + log(acc[0]) * acc[1]);
}

// ---------------- launch ----------------
extern "C" void kernel_launch(void* const* d_in, const int* in_sizes, int n_in,
                              void* d_out, int out_size) {
    const float* theta = (const float*)d_in[0];
    const float* emb   = (const float*)d_in[1];
    float* out = (float*)d_out;

    cudaFuncSetAttribute((const void*)gemm_sym,
                         cudaFuncAttributeMaxDynamicSharedMemorySize, GEMM_SMEM);

    prep<<<D, F>>>(theta, emb);
    gemm_sym<<<2 * NBLK, 256, GEMM_SMEM>>>(theta);
    rowsum<<<D / 8, 256>>>();
    sinkhorn_kernel<<<NB, NT>>>();
    kl_partial<<<NKB, NT>>>();
    finalize<<<1, NKB>>>(out);
}

// round 10
// speedup vs baseline: 1.5858x; 1.0170x over previous
#include <cuda_runtime.h>
#include <cuda_fp16.h>
#include <cstdint>
#include <math.h>

// Problem constants
constexpr int   D       = 2048;
constexpr int   F       = 256;
constexpr float ALPHA   = 0.005f;   // SINKHORN_ALPHA
constexpr float STOPTHR = 0.005f;
constexpr float EPSF    = 1e-16f;
constexpr int   MAXIT   = 500;

// Launch shapes
constexpr int NB   = 128;         // persistent sinkhorn blocks
constexpr int NT   = 256;
constexpr int RPB  = D / NB;      // 16 rows per block
constexpr int NKB  = 256;
constexpr int NBLK = 136;         // triangular 128x128 tile count: 16*17/2

// GEMM smem: two 128x132 u32 tiles (tf32), epilogue reuses tile A as 128x132 f32
constexpr int PITCH = 132;
constexpr int TILEW = 128 * PITCH;            // words per tile
constexpr int GEMM_SMEM = 2 * TILEW * 4;      // 135168 bytes

typedef unsigned long long ull;

// ---------------- device scratch ----------------
__device__ __half d_Kh[(size_t)D * D];    // 8 MB: K = exp(-alpha*C), fp16, symmetric
__device__ float  d_G[(size_t)D * D];     // 16 MB: Ghat = ehat ehat^T, symmetric
__device__ float  d_ehat[D * F];
__device__ float  d_sq[D];
__device__ float  d_invr[D];
__device__ float  d_u[D];
__device__ float  d_v[D];
__device__ float  d_errpart[12 * NB];
__device__ float  d_errglob[12];          // broadcast err per check (uniform exit)
__device__ double d_part[3 * NKB];
__device__ unsigned d_flags[NB];

// ---------------- f32x2 helpers (used in sinkhorn dot) ----------------
__device__ __forceinline__ ull pk2(float lo, float hi) {
    ull r; asm("mov.b64 %0,{%1,%2};" : "=l"(r) : "f"(lo), "f"(hi)); return r;
}
__device__ __forceinline__ float2 up2(ull v) {
    float2 f; asm("mov.b64 {%0,%1},%2;" : "=f"(f.x), "=f"(f.y) : "l"(v)); return f;
}
__device__ __forceinline__ void fma2(ull& d, ull a, ull b) {
    asm("fma.rn.f32x2 %0,%1,%2,%0;" : "+l"(d) : "l"(a), "l"(b));
}
__device__ __forceinline__ ull h2f2(unsigned h) {
    const float2 f = __half22float2(*reinterpret_cast<const __half2*>(&h));
    return pk2(f.x, f.y);
}

// ---------------- tf32 mma helpers ----------------
__device__ __forceinline__ uint32_t f2tf32(float f) {
    uint32_t r; asm("cvt.rna.tf32.f32 %0,%1;" : "=r"(r) : "f"(f)); return r;
}
__device__ __forceinline__ void mma_tf32(float* c, const uint32_t* a, const uint32_t* b) {
    asm("mma.sync.aligned.m16n8k8.row.col.f32.tf32.tf32.f32 "
        "{%0,%1,%2,%3},{%4,%5,%6,%7},{%8,%9},{%0,%1,%2,%3};"
        : "+f"(c[0]), "+f"(c[1]), "+f"(c[2]), "+f"(c[3])
        : "r"(a[0]), "r"(a[1]), "r"(a[2]), "r"(a[3]), "r"(b[0]), "r"(b[1]));
}

__device__ __forceinline__ float warp_red(float s) {
#pragma unroll
    for (int o = 16; o; o >>= 1) s += __shfl_xor_sync(0xffffffffu, s, o);
    return s;
}

// COHERENT poll: ld.relaxed.gpu -> LDG.E.STRONG.GPU, which bypasses the
// non-coherent L1. The previous ld.global.cg poll cached the flag line in L1
// (sm_103a SASS has no .CG coherence encoding -> plain LDG), so every re-poll
// hit a STALE line and the barrier only completed on natural L1 eviction
// (~11us per barrier = nearly all of sinkhorn's 59us for ~5 barriers).
__device__ __forceinline__ unsigned poll_flag(const unsigned* p) {
    unsigned v;
    asm volatile("ld.relaxed.gpu.global.u32 %0, [%1];" : "=r"(v) : "l"(p) : "memory");
    return v;
}

// Distributed flag grid barrier with full release semantics (every thread
// fences its own stores before the block-wide sync; tid 0 then publishes).
__device__ __forceinline__ void gbar(unsigned ep, int tid, int bid) {
    __threadfence();
    __syncthreads();
    if (tid == 0) __stcg(&d_flags[bid], ep);
    if (tid < 32) {
        int spins = 0;
        for (;;) {
            int ok = 1;
#pragma unroll
            for (int k = 0; k < NB / 32; k++)
                if (poll_flag(&d_flags[tid * (NB / 32) + k]) < ep) ok = 0;
            if (__all_sync(0xffffffffu, ok)) break;
            if (++spins > 65536) __nanosleep(64);   // safety fallback
        }
        __threadfence();
    }
    __syncthreads();
}

// ---------------- prep: sq, ehat, flag reset ----------------
__global__ void __launch_bounds__(F) prep(const float* __restrict__ theta,
                                          const float* __restrict__ emb) {
    const int row = blockIdx.x, tid = threadIdx.x;
    if (tid == 0 && row < NB) d_flags[row] = 0u;

    const float t = theta[row * F + tid];
    const float e = emb[row * F + tid];
    float a = t * t, b = e * e;
#pragma unroll
    for (int o = 16; o; o >>= 1) {
        a += __shfl_xor_sync(0xffffffffu, a, o);
        b += __shfl_xor_sync(0xffffffffu, b, o);
    }
    __shared__ float sa[8], sb[8];
    __shared__ float s_inv;
    const int wid = tid >> 5, lane = tid & 31;
    if (lane == 0) { sa[wid] = a; sb[wid] = b; }
    __syncthreads();
    if (tid == 0) {
        float ta = 0.f, tb = 0.f;
#pragma unroll
        for (int i = 0; i < 8; i++) { ta += sa[i]; tb += sb[i]; }
        d_sq[row] = ta;
        s_inv = 1.0f / sqrtf(tb);
    }
    __syncthreads();
    d_ehat[row * F + tid] = e * s_inv;
}

// ---------------- symmetric fused GEMM — tf32 tensor cores --------------
// bid in [0, NBLK)      : K (fp16 out) = exp(-alpha*max(sq_i+sq_j-2*theta theta^T,0))
// bid in [NBLK, 2*NBLK) : Ghat (fp32 out) = ehat ehat^T
// 128x128 tile per block, 8 warps x (64x32) warp tiles of m16n8k8 tf32 mma.
// Lower-triangle blocks only; smem-transpose epilogue -> coalesced mirror store.
__global__ void __launch_bounds__(256, 1) gemm_sym(const float* __restrict__ theta) {
    extern __shared__ uint32_t smw[];
    uint32_t* As = smw;            // [128][PITCH] tf32
    uint32_t* Bs = smw + TILEW;    // [128][PITCH] tf32

    const int bid = blockIdx.x;
    const bool modeK = (bid < NBLK);
    const int tb = modeK ? bid : bid - NBLK;
    const float* __restrict__ X = modeK ? theta : (const float*)d_ehat;

    // triangular index -> (ib, jb), ib >= jb
    int ib = (int)((sqrtf(8.0f * (float)tb + 1.0f) - 1.0f) * 0.5f);
    while ((ib + 1) * (ib + 2) / 2 <= tb) ib++;
    while (ib * (ib + 1) / 2 > tb) ib--;
    const int jb = tb - ib * (ib + 1) / 2;
    const int r0 = ib * 128, c0 = jb * 128;

    const int tid  = threadIdx.x;
    const int wid  = tid >> 5, lane = tid & 31;
    const int g    = lane >> 2, t = lane & 3;   // fragment group / thread-in-group
    const int wm   = wid >> 2,  wn = wid & 3;   // warp tile: rows wm*64, cols wn*32

    float c[4][4][4];
#pragma unroll
    for (int am = 0; am < 4; am++)
#pragma unroll
        for (int bn = 0; bn < 4; bn++)
#pragma unroll
            for (int e = 0; e < 4; e++) c[am][bn][e] = 0.0f;

    for (int kc = 0; kc < 2; kc++) {           // two 128-wide K chunks
        // stage: fp32 -> tf32 into padded smem (k-contiguous rows)
        for (int idx = tid; idx < 128 * 32; idx += 256) {
            const int r = idx >> 5, q = (idx & 31) * 4;
            const float4 av = *(const float4*)(X + (size_t)(r0 + r) * F + kc * 128 + q);
            uint4 ua;
            ua.x = f2tf32(av.x); ua.y = f2tf32(av.y);
            ua.z = f2tf32(av.z); ua.w = f2tf32(av.w);
            *(uint4*)&As[r * PITCH + q] = ua;
            const float4 bv = *(const float4*)(X + (size_t)(c0 + r) * F + kc * 128 + q);
            uint4 ub;
            ub.x = f2tf32(bv.x); ub.y = f2tf32(bv.y);
            ub.z = f2tf32(bv.z); ub.w = f2tf32(bv.w);
            *(uint4*)&Bs[r * PITCH + q] = ub;
        }
        __syncthreads();

#pragma unroll 4
        for (int s = 0; s < 16; s++) {         // k-steps of 8
            uint32_t a[4][4], b[4][2];
#pragma unroll
            for (int am = 0; am < 4; am++) {
                const uint32_t* p = As + (wm * 64 + am * 16 + g) * PITCH + s * 8 + t;
                a[am][0] = p[0];
                a[am][1] = p[8 * PITCH];
                a[am][2] = p[4];
                a[am][3] = p[8 * PITCH + 4];
            }
#pragma unroll
            for (int bn = 0; bn < 4; bn++) {
                const uint32_t* p = Bs + (wn * 32 + bn * 8 + g) * PITCH + s * 8 + t;
                b[bn][0] = p[0];
                b[bn][1] = p[4];
            }
#pragma unroll
            for (int am = 0; am < 4; am++)
#pragma unroll
                for (int bn = 0; bn < 4; bn++)
                    mma_tf32(c[am][bn], a[am], b[bn]);
        }
        __syncthreads();                        // before next stage overwrites
    }

    // ---- epilogue: fragments -> smem (reuse As region), then coalesced stores
    float* Ct = (float*)smw;                    // [128][PITCH]
#pragma unroll
    for (int am = 0; am < 4; am++) {
        const int r = wm * 64 + am * 16 + g;
#pragma unroll
        for (int bn = 0; bn < 4; bn++) {
            const int cc = wn * 32 + bn * 8 + 2 * t;
            *(float2*)&Ct[r * PITCH + cc]       = make_float2(c[am][bn][0], c[am][bn][1]);
            *(float2*)&Ct[(r + 8) * PITCH + cc] = make_float2(c[am][bn][2], c[am][bn][3]);
        }
    }
    __syncthreads();

    if (modeK) {
        // normal rows (coalesced)
        for (int idx = tid; idx < 128 * 32; idx += 256) {
            const int r = idx >> 5, q = (idx & 31) * 4;
            const float4 cv = *(const float4*)&Ct[r * PITCH + q];
            const float sr = __ldg(&d_sq[r0 + r]);
            union { __half h[4]; uint2 u; } pk;
            pk.h[0] = __float2half_rn(__expf(-ALPHA * fmaxf(sr + __ldg(&d_sq[c0 + q + 0]) - 2.0f * cv.x, 0.0f)));
            pk.h[1] = __float2half_rn(__expf(-ALPHA * fmaxf(sr + __ldg(&d_sq[c0 + q + 1]) - 2.0f * cv.y, 0.0f)));
            pk.h[2] = __float2half_rn(__expf(-ALPHA * fmaxf(sr + __ldg(&d_sq[c0 + q + 2]) - 2.0f * cv.z, 0.0f)));
            pk.h[3] = __float2half_rn(__expf(-ALPHA * fmaxf(sr + __ldg(&d_sq[c0 + q + 3]) - 2.0f * cv.w, 0.0f)));
            *(uint2*)(d_Kh + (size_t)(r0 + r) * D + c0 + q) = pk.u;
        }
        // mirror rows: lanes along m -> conflict-free column reads of Ct
        for (int idx = tid; idx < 128 * 32; idx += 256) {
            const int m = idx & 127, q = (idx >> 7) * 4;
            const float sm = __ldg(&d_sq[c0 + m]);
            union { __half h[4]; uint2 u; } pk;
#pragma unroll
            for (int e = 0; e < 4; e++) {
                const float v = Ct[(q + e) * PITCH + m];
                pk.h[e] = __float2half_rn(__expf(-ALPHA * fmaxf(sm + __ldg(&d_sq[r0 + q + e]) - 2.0f * v, 0.0f)));
            }
            *(uint2*)(d_Kh + (size_t)(c0 + m) * D + r0 + q) = pk.u;
        }
    } else {
        for (int idx = tid; idx < 128 * 32; idx += 256) {
            const int r = idx >> 5, q = (idx & 31) * 4;
            *(float4*)(d_G + (size_t)(r0 + r) * D + c0 + q) = *(const float4*)&Ct[r * PITCH + q];
        }
        for (int idx = tid; idx < 128 * 32; idx += 256) {
            const int m = idx & 127, q = (idx >> 7) * 4;
            float4 v;
            v.x = Ct[(q + 0) * PITCH + m];
            v.y = Ct[(q + 1) * PITCH + m];
            v.z = Ct[(q + 2) * PITCH + m];
            v.w = Ct[(q + 3) * PITCH + m];
            *(float4*)(d_G + (size_t)(c0 + m) * D + r0 + q) = v;
        }
    }
}

// ---------------- rowsum of Ghat -> invr ----------------
__global__ void __launch_bounds__(256) rowsum() {
    const int row  = blockIdx.x * 8 + (threadIdx.x >> 5);
    const int lane = threadIdx.x & 31;
    const float4* g = (const float4*)(d_G + (size_t)row * D);
    float s = 0.f;
#pragma unroll
    for (int it = 0; it < D / 128; it++) {
        const float4 v = g[lane + 32 * it];
        s += (v.x + v.y) + (v.z + v.w);
    }
    s = warp_red(s);
    if (lane == 0) d_invr[row] = 1.0f / s;
}

// two interleaved fp16 row-dots against smem fp32 vector, f32x2 accumulation
__device__ __forceinline__ void row_dot2h(const __half* __restrict__ K0,
                                          const __half* __restrict__ K1,
                                          const float* sx, int lane,
                                          float& o0, float& o1) {
    const uint4* a = (const uint4*)K0;   // 8 halves per uint4, 256 per row
    const uint4* b = (const uint4*)K1;
    ull s0a = 0ULL, s0b = 0ULL, s1a = 0ULL, s1b = 0ULL;
#pragma unroll
    for (int it = 0; it < 8; it++) {
        const int o = lane + 32 * it;
        const uint4 k0 = __ldg(a + o);
        const uint4 k1 = __ldg(b + o);
        const ulonglong2 x01 = *(const ulonglong2*)(sx + o * 8);
        const ulonglong2 x23 = *(const ulonglong2*)(sx + o * 8 + 4);
        fma2(s0a, h2f2(k0.x), x01.x); fma2(s0b, h2f2(k0.y), x01.y);
        fma2(s0a, h2f2(k0.z), x23.x); fma2(s0b, h2f2(k0.w), x23.y);
        fma2(s1a, h2f2(k1.x), x01.x); fma2(s1b, h2f2(k1.y), x01.y);
        fma2(s1a, h2f2(k1.z), x23.x); fma2(s1b, h2f2(k1.w), x23.y);
    }
    const float2 p0 = up2(s0a), q0 = up2(s0b);
    const float2 p1 = up2(s1a), q1 = up2(s1b);
    o0 = warp_red((p0.x + p0.y) + (q0.x + q0.y));
    o1 = warp_red((p1.x + p1.y) + (q1.x + q1.y));
}

// ---------------- persistent Sinkhorn (K symmetric => K^T u == K u) -------------
__global__ void __launch_bounds__(NT, 1) sinkhorn_kernel() {
    __shared__ float sx[D];
    __shared__ float sred[RPB];
    const int tid = threadIdx.x, bid = blockIdx.x;
    const int wid = tid >> 5, lane = tid & 31;
    const int row0 = bid * RPB + wid * 2;
    const float AB = 1.0f / (float)D;

    if (tid < RPB) { d_u[bid * RPB + tid] = 1.0f; d_v[bid * RPB + tid] = 1.0f; }

    unsigned ep = 1;
    gbar(ep, tid, bid); ep++;

    float err = 1.0f;
    int cpt = 0;
    while (err > STOPTHR && cpt < MAXIT) {
        // v = b / (K u + eps)
        for (int i = tid; i < D / 4; i += NT)
            ((float4*)sx)[i] = __ldcg(((const float4*)d_u) + i);
        __syncthreads();
        {
            float s0, s1;
            row_dot2h(d_Kh + (size_t)row0 * D, d_Kh + (size_t)(row0 + 1) * D, sx, lane, s0, s1);
            if (lane == 0) {
                d_v[row0]     = AB / (s0 + EPSF);
                d_v[row0 + 1] = AB / (s1 + EPSF);
            }
        }
        gbar(ep, tid, bid); ep++;

        // u = a / (K v + eps)
        for (int i = tid; i < D / 4; i += NT)
            ((float4*)sx)[i] = __ldcg(((const float4*)d_v) + i);
        __syncthreads();
        {
            float s0, s1;
            row_dot2h(d_Kh + (size_t)row0 * D, d_Kh + (size_t)(row0 + 1) * D, sx, lane, s0, s1);
            if (lane == 0) {
                d_u[row0]     = AB / (s0 + EPSF);
                d_u[row0 + 1] = AB / (s1 + EPSF);
            }
        }
        gbar(ep, tid, bid); ep++;

        cpt++;
        if (cpt % 50 == 1) {
            // err = sum_i | v_i * (K u_new)_i - b |
            for (int i = tid; i < D / 4; i += NT)
                ((float4*)sx)[i] = __ldcg(((const float4*)d_u) + i);
            __syncthreads();
            {
                float s0, s1;
                row_dot2h(d_Kh + (size_t)row0 * D, d_Kh + (size_t)(row0 + 1) * D, sx, lane, s0, s1);
                if (lane == 0) {
                    sred[wid * 2]     = fabsf(__ldcg(&d_v[row0])     * s0 - AB);
                    sred[wid * 2 + 1] = fabsf(__ldcg(&d_v[row0 + 1]) * s1 - AB);
                }
            }
            __syncthreads();
            const int chk = cpt / 50;
            if (tid == 0) {
                float e = 0.f;
#pragma unroll
                for (int i = 0; i < RPB; i++) e += sred[i];
                d_errpart[chk * NB + bid] = e;
            }
            gbar(ep, tid, bid); ep++;
            // block 0 reduces and broadcasts one float: uniform exit.
            if (bid == 0 && tid == 0) {
                float e = 0.f;
                for (int i = 0; i < NB; i++) e += __ldcg(&d_errpart[chk * NB + i]);
                d_errglob[chk] = e;
            }
            gbar(ep, tid, bid); ep++;
            err = __ldcg(&d_errglob[chk]);
        }
    }
}

// ---------------- KL reduction ----------------
// Qt_ij = max(u_i K_ij v_j, 1e-6), S = sum Qt, P_ij = G_ij*(invr_i+invr_j)/2
// kl = sum P*log(P/Qt) + log(S) * sum P
__global__ void __launch_bounds__(NT) kl_partial() {
    const int tid = threadIdx.x;
    constexpr int TOT8 = D * D / 8;
    const int stride = NKB * NT;
    const uint4*  Kv = (const uint4*)d_Kh;
    const float4* Gv = (const float4*)d_G;
    const float4* Vv = (const float4*)d_v;
    const float4* Rv = (const float4*)d_invr;

    float sS = 0.f, sP = 0.f, sK = 0.f;
    for (int g8 = blockIdx.x * NT + tid; g8 < TOT8; g8 += stride) {
        const int i  = g8 >> 8;
        const int c8 = g8 & 255;
        const uint4 kh = Kv[g8];
        const float4 g0 = Gv[g8 * 2];
        const float4 g1 = Gv[g8 * 2 + 1];
        const float4 v0 = Vv[c8 * 2];
        const float4 v1 = Vv[c8 * 2 + 1];
        const float4 r0 = Rv[c8 * 2];
        const float4 r1 = Rv[c8 * 2 + 1];
        const float ui  = d_u[i];
        const float iri = d_invr[i];

        const float2 ka = __half22float2(*(const __half2*)&kh.x);
        const float2 kb = __half22float2(*(const __half2*)&kh.y);
        const float2 kc = __half22float2(*(const __half2*)&kh.z);
        const float2 kd = __half22float2(*(const __half2*)&kh.w);

        float q, p;
        q = fmaxf(ui * ka.x * v0.x, 1e-6f); p = g0.x * (0.5f * (iri + r0.x));
        sS += q; sP += p; sK += p * __logf(__fdividef(p, q));
        q = fmaxf(ui * ka.y * v0.y, 1e-6f); p = g0.y * (0.5f * (iri + r0.y));
        sS += q; sP += p; sK += p * __logf(__fdividef(p, q));
        q = fmaxf(ui * kb.x * v0.z, 1e-6f); p = g0.z * (0.5f * (iri + r0.z));
        sS += q; sP += p; sK += p * __logf(__fdividef(p, q));
        q = fmaxf(ui * kb.y * v0.w, 1e-6f); p = g0.w * (0.5f * (iri + r0.w));
        sS += q; sP += p; sK += p * __logf(__fdividef(p, q));
        q = fmaxf(ui * kc.x * v1.x, 1e-6f); p = g1.x * (0.5f * (iri + r1.x));
        sS += q; sP += p; sK += p * __logf(__fdividef(p, q));
        q = fmaxf(ui * kc.y * v1.y, 1e-6f); p = g1.y * (0.5f * (iri + r1.y));
        sS += q; sP += p; sK += p * __logf(__fdividef(p, q));
        q = fmaxf(ui * kd.x * v1.z, 1e-6f); p = g1.z * (0.5f * (iri + r1.z));
        sS += q; sP += p; sK += p * __logf(__fdividef(p, q));
        q = fmaxf(ui * kd.y * v1.w, 1e-6f); p = g1.w * (0.5f * (iri + r1.w));
        sS += q; sP += p; sK += p * __logf(__fdividef(p, q));
    }

    __shared__ double sd[NT];
    const double vals[3] = {(double)sS, (double)sP, (double)sK};
#pragma unroll
    for (int t = 0; t < 3; t++) {
        sd[tid] = vals[t];
        __syncthreads();
        for (int o = NT / 2; o; o >>= 1) {
            if (tid < o) sd[tid] += sd[tid + o];
            __syncthreads();
        }
        if (tid == 0) d_part[t * NKB + blockIdx.x] = sd[0];
        __syncthreads();
    }
}

__global__ void __launch_bounds__(NKB) finalize(float* out) {
    __shared__ double sd[NKB];
    const int tid = threadIdx.x;
    double acc[3];
#pragma unroll
    for (int t = 0; t < 3; t++) {
        sd[tid] = d_part[t * NKB + tid];
        __syncthreads();
        for (int o = NKB / 2; o; o >>= 1) {
            if (tid < o) sd[tid] += sd[tid + o];
            __syncthreads();
        }
        acc[t] = sd[0];
        __syncthreads();
    }
    if (tid == 0) out[0] = (float)(acc[2] + log(acc[0]) * acc[1]);
}

// ---------------- launch ----------------
extern "C" void kernel_launch(void* const* d_in, const int* in_sizes, int n_in,
                              void* d_out, int out_size) {
    const float* theta = (const float*)d_in[0];
    const float* emb   = (const float*)d_in[1];
    float* out = (float*)d_out;

    cudaFuncSetAttribute((const void*)gemm_sym,
                         cudaFuncAttributeMaxDynamicSharedMemorySize, GEMM_SMEM);

    prep<<<D, F>>>(theta, emb);
    gemm_sym<<<2 * NBLK, 256, GEMM_SMEM>>>(theta);
    rowsum<<<D / 8, 256>>>();
    sinkhorn_kernel<<<NB, NT>>>();
    kl_partial<<<NKB, NT>>>();
    finalize<<<1, NKB>>>(out);
}

// round 11
// speedup vs baseline: 1.6859x; 1.0631x over previous
#include <cuda_runtime.h>
#include <cuda_fp16.h>
#include <cstdint>
#include <math.h>

// Problem constants
constexpr int   D       = 2048;
constexpr int   F       = 256;
constexpr float ALPHA   = 0.005f;   // SINKHORN_ALPHA
constexpr float STOPTHR = 0.005f;
constexpr float EPSF    = 1e-16f;
constexpr int   MAXIT   = 500;

// Launch shapes
constexpr int NB   = 128;         // persistent sinkhorn blocks
constexpr int NT   = 256;
constexpr int RPB  = D / NB;      // 16 rows per block
constexpr int NKB  = 256;
constexpr int NBLK = 136;         // triangular 128x128 tile count: 16*17/2

// GEMM smem: two 128x68 u32 tiles (tf32, K-chunk=64) -> 69.6KB -> 2 CTAs/SM,
// all 272 blocks in ONE wave. Epilogue reuses the union as 128x132 f32.
constexpr int PITCH2  = 68;                   // mma tile pitch (words)
constexpr int TILEW2  = 128 * PITCH2;         // words per tile
constexpr int PITCH_C = 132;                  // epilogue pitch (words)
constexpr int GEMM_SMEM = 2 * TILEW2 * 4;     // 69632 bytes (>= 128*132*4 = 67584)

typedef unsigned long long ull;

// ---------------- device scratch ----------------
__device__ __half d_Kh[(size_t)D * D];    // 8 MB: K = exp(-alpha*C), fp16, symmetric
__device__ float  d_G[(size_t)D * D];     // 16 MB: Ghat = ehat ehat^T, symmetric
__device__ float  d_ehat[D * F];
__device__ float  d_sq[D];
__device__ float  d_invr[D];
__device__ float  d_u[D];
__device__ float  d_v[D];
__device__ float  d_errpart[12 * NB];
__device__ float  d_errglob[12];          // broadcast err per check (uniform exit)
__device__ double d_part[3 * NKB];
__device__ unsigned d_flags[NB];

// ---------------- f32x2 helpers (used in sinkhorn dot) ----------------
__device__ __forceinline__ ull pk2(float lo, float hi) {
    ull r; asm("mov.b64 %0,{%1,%2};" : "=l"(r) : "f"(lo), "f"(hi)); return r;
}
__device__ __forceinline__ float2 up2(ull v) {
    float2 f; asm("mov.b64 {%0,%1},%2;" : "=f"(f.x), "=f"(f.y) : "l"(v)); return f;
}
__device__ __forceinline__ void fma2(ull& d, ull a, ull b) {
    asm("fma.rn.f32x2 %0,%1,%2,%0;" : "+l"(d) : "l"(a), "l"(b));
}
__device__ __forceinline__ ull h2f2(unsigned h) {
    const float2 f = __half22float2(*reinterpret_cast<const __half2*>(&h));
    return pk2(f.x, f.y);
}

// ---------------- tf32 mma helpers ----------------
__device__ __forceinline__ uint32_t f2tf32(float f) {
    uint32_t r; asm("cvt.rna.tf32.f32 %0,%1;" : "=r"(r) : "f"(f)); return r;
}
__device__ __forceinline__ void mma_tf32(float* c, const uint32_t* a, const uint32_t* b) {
    asm("mma.sync.aligned.m16n8k8.row.col.f32.tf32.tf32.f32 "
        "{%0,%1,%2,%3},{%4,%5,%6,%7},{%8,%9},{%0,%1,%2,%3};"
        : "+f"(c[0]), "+f"(c[1]), "+f"(c[2]), "+f"(c[3])
        : "r"(a[0]), "r"(a[1]), "r"(a[2]), "r"(a[3]), "r"(b[0]), "r"(b[1]));
}

__device__ __forceinline__ float warp_red(float s) {
#pragma unroll
    for (int o = 16; o; o >>= 1) s += __shfl_xor_sync(0xffffffffu, s, o);
    return s;
}

// Grid barrier, cooperative-groups grid.sync pattern:
//   __syncthreads (CTA-scope happens-before to tid0)
//   tid0: st.release.gpu of the epoch flag     (NO per-thread __threadfence!)
//   warp0: poll all flags with ld.acquire.gpu
//   __syncthreads (propagate acquire to the block)
// The previous barrier ran __threadfence() in ALL 256 threads, which on sm_103a
// emits MEMBAR.GPU + CCTL.IVALL (full L1D invalidate) -> the dominant ~10us/barrier
// cost that was invariant to the poll mechanism.
__device__ __forceinline__ void gbar(unsigned ep, int tid, int bid) {
    __syncthreads();
    if (tid == 0)
        asm volatile("st.release.gpu.global.u32 [%0], %1;"
                     :: "l"(&d_flags[bid]), "r"(ep) : "memory");
    if (tid < 32) {
        int spins = 0;
        for (;;) {
            int ok = 1;
#pragma unroll
            for (int k = 0; k < NB / 32; k++) {
                unsigned v;
                asm volatile("ld.acquire.gpu.global.u32 %0, [%1];"
                             : "=r"(v) : "l"(&d_flags[tid * (NB / 32) + k]) : "memory");
                if (v < ep) ok = 0;
            }
            if (__all_sync(0xffffffffu, ok)) break;
            if (++spins > 100000) __nanosleep(128);   // safety valve only
        }
    }
    __syncthreads();
}

// ---------------- prep: sq, ehat, flag reset ----------------
__global__ void __launch_bounds__(F) prep(const float* __restrict__ theta,
                                          const float* __restrict__ emb) {
    const int row = blockIdx.x, tid = threadIdx.x;
    if (tid == 0 && row < NB) d_flags[row] = 0u;

    const float t = theta[row * F + tid];
    const float e = emb[row * F + tid];
    float a = t * t, b = e * e;
#pragma unroll
    for (int o = 16; o; o >>= 1) {
        a += __shfl_xor_sync(0xffffffffu, a, o);
        b += __shfl_xor_sync(0xffffffffu, b, o);
    }
    __shared__ float sa[8], sb[8];
    __shared__ float s_inv;
    const int wid = tid >> 5, lane = tid & 31;
    if (lane == 0) { sa[wid] = a; sb[wid] = b; }
    __syncthreads();
    if (tid == 0) {
        float ta = 0.f, tb = 0.f;
#pragma unroll
        for (int i = 0; i < 8; i++) { ta += sa[i]; tb += sb[i]; }
        d_sq[row] = ta;
        s_inv = 1.0f / sqrtf(tb);
    }
    __syncthreads();
    d_ehat[row * F + tid] = e * s_inv;
}

// ---------------- symmetric fused GEMM — tf32 tensor cores --------------
// bid in [0, NBLK)      : K (fp16 out) = exp(-alpha*max(sq_i+sq_j-2*theta theta^T,0))
// bid in [NBLK, 2*NBLK) : Ghat (fp32 out) = ehat ehat^T
// 128x128 tile per block, 8 warps x (64x32) warp tiles of m16n8k8 tf32 mma.
// K-chunk = 64 -> 69.6KB smem -> 2 CTAs/SM -> single wave for all 272 blocks.
__global__ void __launch_bounds__(256, 2) gemm_sym(const float* __restrict__ theta) {
    extern __shared__ uint32_t smw[];
    uint32_t* As = smw;             // [128][PITCH2] tf32
    uint32_t* Bs = smw + TILEW2;    // [128][PITCH2] tf32

    const int bid = blockIdx.x;
    const bool modeK = (bid < NBLK);
    const int tb = modeK ? bid : bid - NBLK;
    const float* __restrict__ X = modeK ? theta : (const float*)d_ehat;

    // triangular index -> (ib, jb), ib >= jb
    int ib = (int)((sqrtf(8.0f * (float)tb + 1.0f) - 1.0f) * 0.5f);
    while ((ib + 1) * (ib + 2) / 2 <= tb) ib++;
    while (ib * (ib + 1) / 2 > tb) ib--;
    const int jb = tb - ib * (ib + 1) / 2;
    const int r0 = ib * 128, c0 = jb * 128;

    const int tid  = threadIdx.x;
    const int wid  = tid >> 5, lane = tid & 31;
    const int g    = lane >> 2, t = lane & 3;   // fragment group / thread-in-group
    const int wm   = wid >> 2,  wn = wid & 3;   // warp tile: rows wm*64, cols wn*32

    float c[4][4][4];
#pragma unroll
    for (int am = 0; am < 4; am++)
#pragma unroll
        for (int bn = 0; bn < 4; bn++)
#pragma unroll
            for (int e = 0; e < 4; e++) c[am][bn][e] = 0.0f;

    for (int kc = 0; kc < 4; kc++) {           // four 64-wide K chunks
        // stage: fp32 -> tf32 into padded smem (k-contiguous rows)
        for (int idx = tid; idx < 128 * 16; idx += 256) {
            const int r = idx >> 4, q = (idx & 15) * 4;
            const float4 av = *(const float4*)(X + (size_t)(r0 + r) * F + kc * 64 + q);
            uint4 ua;
            ua.x = f2tf32(av.x); ua.y = f2tf32(av.y);
            ua.z = f2tf32(av.z); ua.w = f2tf32(av.w);
            *(uint4*)&As[r * PITCH2 + q] = ua;
            const float4 bv = *(const float4*)(X + (size_t)(c0 + r) * F + kc * 64 + q);
            uint4 ub;
            ub.x = f2tf32(bv.x); ub.y = f2tf32(bv.y);
            ub.z = f2tf32(bv.z); ub.w = f2tf32(bv.w);
            *(uint4*)&Bs[r * PITCH2 + q] = ub;
        }
        __syncthreads();

#pragma unroll 4
        for (int s = 0; s < 8; s++) {          // k-steps of 8 within the chunk
            uint32_t a[4][4], b[4][2];
#pragma unroll
            for (int am = 0; am < 4; am++) {
                const uint32_t* p = As + (wm * 64 + am * 16 + g) * PITCH2 + s * 8 + t;
                a[am][0] = p[0];
                a[am][1] = p[8 * PITCH2];
                a[am][2] = p[4];
                a[am][3] = p[8 * PITCH2 + 4];
            }
#pragma unroll
            for (int bn = 0; bn < 4; bn++) {
                const uint32_t* p = Bs + (wn * 32 + bn * 8 + g) * PITCH2 + s * 8 + t;
                b[bn][0] = p[0];
                b[bn][1] = p[4];
            }
#pragma unroll
            for (int am = 0; am < 4; am++)
#pragma unroll
                for (int bn = 0; bn < 4; bn++)
                    mma_tf32(c[am][bn], a[am], b[bn]);
        }
        __syncthreads();                        // before next stage overwrites
    }

    // ---- epilogue: fragments -> smem (reuse whole region), then coalesced stores
    float* Ct = (float*)smw;                    // [128][PITCH_C]
#pragma unroll
    for (int am = 0; am < 4; am++) {
        const int r = wm * 64 + am * 16 + g;
#pragma unroll
        for (int bn = 0; bn < 4; bn++) {
            const int cc = wn * 32 + bn * 8 + 2 * t;
            *(float2*)&Ct[r * PITCH_C + cc]       = make_float2(c[am][bn][0], c[am][bn][1]);
            *(float2*)&Ct[(r + 8) * PITCH_C + cc] = make_float2(c[am][bn][2], c[am][bn][3]);
        }
    }
    __syncthreads();

    if (modeK) {
        // normal rows (coalesced)
        for (int idx = tid; idx < 128 * 32; idx += 256) {
            const int r = idx >> 5, q = (idx & 31) * 4;
            const float4 cv = *(const float4*)&Ct[r * PITCH_C + q];
            const float sr = __ldg(&d_sq[r0 + r]);
            union { __half h[4]; uint2 u; } pk;
            pk.h[0] = __float2half_rn(__expf(-ALPHA * fmaxf(sr + __ldg(&d_sq[c0 + q + 0]) - 2.0f * cv.x, 0.0f)));
            pk.h[1] = __float2half_rn(__expf(-ALPHA * fmaxf(sr + __ldg(&d_sq[c0 + q + 1]) - 2.0f * cv.y, 0.0f)));
            pk.h[2] = __float2half_rn(__expf(-ALPHA * fmaxf(sr + __ldg(&d_sq[c0 + q + 2]) - 2.0f * cv.z, 0.0f)));
            pk.h[3] = __float2half_rn(__expf(-ALPHA * fmaxf(sr + __ldg(&d_sq[c0 + q + 3]) - 2.0f * cv.w, 0.0f)));
            *(uint2*)(d_Kh + (size_t)(r0 + r) * D + c0 + q) = pk.u;
        }
        // mirror rows: lanes along m -> conflict-free column reads of Ct
        for (int idx = tid; idx < 128 * 32; idx += 256) {
            const int m = idx & 127, q = (idx >> 7) * 4;
            const float sm = __ldg(&d_sq[c0 + m]);
            union { __half h[4]; uint2 u; } pk;
#pragma unroll
            for (int e = 0; e < 4; e++) {
                const float v = Ct[(q + e) * PITCH_C + m];
                pk.h[e] = __float2half_rn(__expf(-ALPHA * fmaxf(sm + __ldg(&d_sq[r0 + q + e]) - 2.0f * v, 0.0f)));
            }
            *(uint2*)(d_Kh + (size_t)(c0 + m) * D + r0 + q) = pk.u;
        }
    } else {
        for (int idx = tid; idx < 128 * 32; idx += 256) {
            const int r = idx >> 5, q = (idx & 31) * 4;
            *(float4*)(d_G + (size_t)(r0 + r) * D + c0 + q) = *(const float4*)&Ct[r * PITCH_C + q];
        }
        for (int idx = tid; idx < 128 * 32; idx += 256) {
            const int m = idx & 127, q = (idx >> 7) * 4;
            float4 v;
            v.x = Ct[(q + 0) * PITCH_C + m];
            v.y = Ct[(q + 1) * PITCH_C + m];
            v.z = Ct[(q + 2) * PITCH_C + m];
            v.w = Ct[(q + 3) * PITCH_C + m];
            *(float4*)(d_G + (size_t)(c0 + m) * D + r0 + q) = v;
        }
    }
}

// ---------------- rowsum of Ghat -> invr ----------------
__global__ void __launch_bounds__(256) rowsum() {
    const int row  = blockIdx.x * 8 + (threadIdx.x >> 5);
    const int lane = threadIdx.x & 31;
    const float4* g = (const float4*)(d_G + (size_t)row * D);
    float s = 0.f;
#pragma unroll
    for (int it = 0; it < D / 128; it++) {
        const float4 v = g[lane + 32 * it];
        s += (v.x + v.y) + (v.z + v.w);
    }
    s = warp_red(s);
    if (lane == 0) d_invr[row] = 1.0f / s;
}

// two interleaved fp16 row-dots against smem fp32 vector, f32x2 accumulation
__device__ __forceinline__ void row_dot2h(const __half* __restrict__ K0,
                                          const __half* __restrict__ K1,
                                          const float* sx, int lane,
                                          float& o0, float& o1) {
    const uint4* a = (const uint4*)K0;   // 8 halves per uint4, 256 per row
    const uint4* b = (const uint4*)K1;
    ull s0a = 0ULL, s0b = 0ULL, s1a = 0ULL, s1b = 0ULL;
#pragma unroll
    for (int it = 0; it < 8; it++) {
        const int o = lane + 32 * it;
        const uint4 k0 = __ldg(a + o);
        const uint4 k1 = __ldg(b + o);
        const ulonglong2 x01 = *(const ulonglong2*)(sx + o * 8);
        const ulonglong2 x23 = *(const ulonglong2*)(sx + o * 8 + 4);
        fma2(s0a, h2f2(k0.x), x01.x); fma2(s0b, h2f2(k0.y), x01.y);
        fma2(s0a, h2f2(k0.z), x23.x); fma2(s0b, h2f2(k0.w), x23.y);
        fma2(s1a, h2f2(k1.x), x01.x); fma2(s1b, h2f2(k1.y), x01.y);
        fma2(s1a, h2f2(k1.z), x23.x); fma2(s1b, h2f2(k1.w), x23.y);
    }
    const float2 p0 = up2(s0a), q0 = up2(s0b);
    const float2 p1 = up2(s1a), q1 = up2(s1b);
    o0 = warp_red((p0.x + p0.y) + (q0.x + q0.y));
    o1 = warp_red((p1.x + p1.y) + (q1.x + q1.y));
}

// ---------------- persistent Sinkhorn (K symmetric => K^T u == K u) -------------
__global__ void __launch_bounds__(NT, 1) sinkhorn_kernel() {
    __shared__ float sx[D];
    __shared__ float sred[RPB];
    const int tid = threadIdx.x, bid = blockIdx.x;
    const int wid = tid >> 5, lane = tid & 31;
    const int row0 = bid * RPB + wid * 2;
    const float AB = 1.0f / (float)D;

    if (tid < RPB) { d_u[bid * RPB + tid] = 1.0f; d_v[bid * RPB + tid] = 1.0f; }

    unsigned ep = 1;
    gbar(ep, tid, bid); ep++;

    float err = 1.0f;
    int cpt = 0;
    while (err > STOPTHR && cpt < MAXIT) {
        // v = b / (K u + eps)
        for (int i = tid; i < D / 4; i += NT)
            ((float4*)sx)[i] = __ldcg(((const float4*)d_u) + i);
        __syncthreads();
        {
            float s0, s1;
            row_dot2h(d_Kh + (size_t)row0 * D, d_Kh + (size_t)(row0 + 1) * D, sx, lane, s0, s1);
            if (lane == 0) {
                d_v[row0]     = AB / (s0 + EPSF);
                d_v[row0 + 1] = AB / (s1 + EPSF);
            }
        }
        gbar(ep, tid, bid); ep++;

        // u = a / (K v + eps)
        for (int i = tid; i < D / 4; i += NT)
            ((float4*)sx)[i] = __ldcg(((const float4*)d_v) + i);
        __syncthreads();
        {
            float s0, s1;
            row_dot2h(d_Kh + (size_t)row0 * D, d_Kh + (size_t)(row0 + 1) * D, sx, lane, s0, s1);
            if (lane == 0) {
                d_u[row0]     = AB / (s0 + EPSF);
                d_u[row0 + 1] = AB / (s1 + EPSF);
            }
        }
        gbar(ep, tid, bid); ep++;

        cpt++;
        if (cpt % 50 == 1) {
            // err = sum_i | v_i * (K u_new)_i - b |
            for (int i = tid; i < D / 4; i += NT)
                ((float4*)sx)[i] = __ldcg(((const float4*)d_u) + i);
            __syncthreads();
            {
                float s0, s1;
                row_dot2h(d_Kh + (size_t)row0 * D, d_Kh + (size_t)(row0 + 1) * D, sx, lane, s0, s1);
                if (lane == 0) {
                    sred[wid * 2]     = fabsf(__ldcg(&d_v[row0])     * s0 - AB);
                    sred[wid * 2 + 1] = fabsf(__ldcg(&d_v[row0 + 1]) * s1 - AB);
                }
            }
            __syncthreads();
            const int chk = cpt / 50;
            if (tid == 0) {
                float e = 0.f;
#pragma unroll
                for (int i = 0; i < RPB; i++) e += sred[i];
                d_errpart[chk * NB + bid] = e;
            }
            gbar(ep, tid, bid); ep++;
            // block 0 reduces and broadcasts one float: uniform exit.
            if (bid == 0 && tid == 0) {
                float e = 0.f;
                for (int i = 0; i < NB; i++) e += __ldcg(&d_errpart[chk * NB + i]);
                d_errglob[chk] = e;
            }
            gbar(ep, tid, bid); ep++;
            err = __ldcg(&d_errglob[chk]);
        }
    }
}

// ---------------- KL reduction ----------------
// Qt_ij = max(u_i K_ij v_j, 1e-6), S = sum Qt, P_ij = G_ij*(invr_i+invr_j)/2
// kl = sum P*log(P/Qt) + log(S) * sum P
__global__ void __launch_bounds__(NT) kl_partial() {
    const int tid = threadIdx.x;
    constexpr int TOT8 = D * D / 8;
    const int stride = NKB * NT;
    const uint4*  Kv = (const uint4*)d_Kh;
    const float4* Gv = (const float4*)d_G;
    const float4* Vv = (const float4*)d_v;
    const float4* Rv = (const float4*)d_invr;

    float sS = 0.f, sP = 0.f, sK = 0.f;
    for (int g8 = blockIdx.x * NT + tid; g8 < TOT8; g8 += stride) {
        const int i  = g8 >> 8;
        const int c8 = g8 & 255;
        const uint4 kh = Kv[g8];
        const float4 g0 = Gv[g8 * 2];
        const float4 g1 = Gv[g8 * 2 + 1];
        const float4 v0 = Vv[c8 * 2];
        const float4 v1 = Vv[c8 * 2 + 1];
        const float4 r0 = Rv[c8 * 2];
        const float4 r1 = Rv[c8 * 2 + 1];
        const float ui  = d_u[i];
        const float iri = d_invr[i];

        const float2 ka = __half22float2(*(const __half2*)&kh.x);
        const float2 kb = __half22float2(*(const __half2*)&kh.y);
        const float2 kc = __half22float2(*(const __half2*)&kh.z);
        const float2 kd = __half22float2(*(const __half2*)&kh.w);

        float q, p;
        q = fmaxf(ui * ka.x * v0.x, 1e-6f); p = g0.x * (0.5f * (iri + r0.x));
        sS += q; sP += p; sK += p * __logf(__fdividef(p, q));
        q = fmaxf(ui * ka.y * v0.y, 1e-6f); p = g0.y * (0.5f * (iri + r0.y));
        sS += q; sP += p; sK += p * __logf(__fdividef(p, q));
        q = fmaxf(ui * kb.x * v0.z, 1e-6f); p = g0.z * (0.5f * (iri + r0.z));
        sS += q; sP += p; sK += p * __logf(__fdividef(p, q));
        q = fmaxf(ui * kb.y * v0.w, 1e-6f); p = g0.w * (0.5f * (iri + r0.w));
        sS += q; sP += p; sK += p * __logf(__fdividef(p, q));
        q = fmaxf(ui * kc.x * v1.x, 1e-6f); p = g1.x * (0.5f * (iri + r1.x));
        sS += q; sP += p; sK += p * __logf(__fdividef(p, q));
        q = fmaxf(ui * kc.y * v1.y, 1e-6f); p = g1.y * (0.5f * (iri + r1.y));
        sS += q; sP += p; sK += p * __logf(__fdividef(p, q));
        q = fmaxf(ui * kd.x * v1.z, 1e-6f); p = g1.z * (0.5f * (iri + r1.z));
        sS += q; sP += p; sK += p * __logf(__fdividef(p, q));
        q = fmaxf(ui * kd.y * v1.w, 1e-6f); p = g1.w * (0.5f * (iri + r1.w));
        sS += q; sP += p; sK += p * __logf(__fdividef(p, q));
    }

    __shared__ double sd[NT];
    const double vals[3] = {(double)sS, (double)sP, (double)sK};
#pragma unroll
    for (int t = 0; t < 3; t++) {
        sd[tid] = vals[t];
        __syncthreads();
        for (int o = NT / 2; o; o >>= 1) {
            if (tid < o) sd[tid] += sd[tid + o];
            __syncthreads();
        }
        if (tid == 0) d_part[t * NKB + blockIdx.x] = sd[0];
        __syncthreads();
    }
}

__global__ void __launch_bounds__(NKB) finalize(float* out) {
    __shared__ double sd[NKB];
    const int tid = threadIdx.x;
    double acc[3];
#pragma unroll
    for (int t = 0; t < 3; t++) {
        sd[tid] = d_part[t * NKB + tid];
        __syncthreads();
        for (int o = NKB / 2; o; o >>= 1) {
            if (tid < o) sd[tid] += sd[tid + o];
            __syncthreads();
        }
        acc[t] = sd[0];
        __syncthreads();
    }
    if (tid == 0) out[0] = (float)(acc[2] + log(acc[0]) * acc[1]);
}

// ---------------- launch ----------------
extern "C" void kernel_launch(void* const* d_in, const int* in_sizes, int n_in,
                              void* d_out, int out_size) {
    const float* theta = (const float*)d_in[0];
    const float* emb   = (const float*)d_in[1];
    float* out = (float*)d_out;

    cudaFuncSetAttribute((const void*)gemm_sym,
                         cudaFuncAttributeMaxDynamicSharedMemorySize, GEMM_SMEM);

    prep<<<D, F>>>(theta, emb);
    gemm_sym<<<2 * NBLK, 256, GEMM_SMEM>>>(theta);
    rowsum<<<D / 8, 256>>>();
    sinkhorn_kernel<<<NB, NT>>>();
    kl_partial<<<NKB, NT>>>();
    finalize<<<1, NKB>>>(out);
}

// round 12
// speedup vs baseline: 1.9205x; 1.1391x over previous
#include <cuda_runtime.h>
#include <cuda_fp16.h>
#include <cstdint>
#include <math.h>

// Problem constants
constexpr int   D       = 2048;
constexpr int   F       = 256;
constexpr float ALPHA   = 0.005f;   // SINKHORN_ALPHA
constexpr float STOPTHR = 0.005f;
constexpr float EPSF    = 1e-16f;
constexpr int   MAXIT   = 500;

// Launch shapes
constexpr int NB   = 128;         // persistent sinkhorn blocks
constexpr int NT   = 256;
constexpr int RPB  = D / NB;      // 16 rows per block
constexpr int NKB  = 256;
constexpr int NBLK = 136;         // triangular 128x128 tile count: 16*17/2

// GEMM smem: two 128x68 u32 tiles (tf32, K-chunk=64) -> 69.6KB -> 2 CTAs/SM,
// all 272 blocks in ONE wave. Epilogue reuses the union as 128x132 f32.
constexpr int PITCH2  = 68;                   // mma tile pitch (words)
constexpr int TILEW2  = 128 * PITCH2;         // words per tile
constexpr int PITCH_C = 132;                  // epilogue pitch (words)
constexpr int GEMM_SMEM = 2 * TILEW2 * 4;     // 69632 bytes (>= 128*132*4 = 67584)

typedef unsigned long long ull;

// ---------------- device scratch ----------------
__device__ __half d_Kh[(size_t)D * D];    // 8 MB: K = exp(-alpha*C), fp16, symmetric
__device__ float  d_G[(size_t)D * D];     // 16 MB: Ghat = ehat ehat^T, symmetric
__device__ float  d_ehat[D * F];
__device__ float  d_sq[D];
__device__ float  d_invr[D];
__device__ float  d_u[D];
__device__ float  d_v[D];
__device__ float  d_errpart[12 * NB];
__device__ double d_part[3 * NKB];
__device__ unsigned d_cnt;                // cumulative grid-barrier counter

// ---------------- f32x2 helpers (used in sinkhorn dot) ----------------
__device__ __forceinline__ ull pk2(float lo, float hi) {
    ull r; asm("mov.b64 %0,{%1,%2};" : "=l"(r) : "f"(lo), "f"(hi)); return r;
}
__device__ __forceinline__ float2 up2(ull v) {
    float2 f; asm("mov.b64 {%0,%1},%2;" : "=f"(f.x), "=f"(f.y) : "l"(v)); return f;
}
__device__ __forceinline__ void fma2(ull& d, ull a, ull b) {
    asm("fma.rn.f32x2 %0,%1,%2,%0;" : "+l"(d) : "l"(a), "l"(b));
}
__device__ __forceinline__ ull h2f2(unsigned h) {
    const float2 f = __half22float2(*reinterpret_cast<const __half2*>(&h));
    return pk2(f.x, f.y);
}

// ---------------- tf32 mma helpers ----------------
__device__ __forceinline__ uint32_t f2tf32(float f) {
    uint32_t r; asm("cvt.rna.tf32.f32 %0,%1;" : "=r"(r) : "f"(f)); return r;
}
__device__ __forceinline__ void mma_tf32(float* c, const uint32_t* a, const uint32_t* b) {
    asm("mma.sync.aligned.m16n8k8.row.col.f32.tf32.tf32.f32 "
        "{%0,%1,%2,%3},{%4,%5,%6,%7},{%8,%9},{%0,%1,%2,%3};"
        : "+f"(c[0]), "+f"(c[1]), "+f"(c[2]), "+f"(c[3])
        : "r"(a[0]), "r"(a[1]), "r"(a[2]), "r"(a[3]), "r"(b[0]), "r"(b[1]));
}

__device__ __forceinline__ float warp_red(float s) {
#pragma unroll
    for (int o = 16; o; o >>= 1) s += __shfl_xor_sync(0xffffffffu, s, o);
    return s;
}

// Grid barrier: single cumulative counter, SINGLE poller per block.
// Previous barriers all had 128 blocks x 32 lanes polling 128 flags packed in
// ~4 L2 sectors -> ~16K load requests per poll sweep funneled into 4 LTS
// partitions, whose serial sector service made every barrier cost ~10us
// REGARDLESS of load flavor (the invariant across rounds 8-11).
// Now: arrive = red.release.gpu.add by tid0 (single-address REDG, ~0.85cyc/op);
// wait = tid0 alone polls ONE word with ld.acquire.gpu; __syncthreads fans out.
__device__ __forceinline__ void gbar(unsigned target, int tid) {
    __syncthreads();
    if (tid == 0) {
        asm volatile("red.release.gpu.global.add.u32 [%0], 1;"
                     :: "l"(&d_cnt) : "memory");
        unsigned v;
        int spins = 0;
        do {
            asm volatile("ld.acquire.gpu.global.u32 %0, [%1];"
                         : "=r"(v) : "l"(&d_cnt) : "memory");
            if (++spins > 100000) __nanosleep(128);   // safety valve only
        } while (v < target);
    }
    __syncthreads();
}

// ---------------- prep: sq, ehat, counter reset ----------------
__global__ void __launch_bounds__(F) prep(const float* __restrict__ theta,
                                          const float* __restrict__ emb) {
    const int row = blockIdx.x, tid = threadIdx.x;
    if (tid == 0 && row == 0) d_cnt = 0u;

    const float t = theta[row * F + tid];
    const float e = emb[row * F + tid];
    float a = t * t, b = e * e;
#pragma unroll
    for (int o = 16; o; o >>= 1) {
        a += __shfl_xor_sync(0xffffffffu, a, o);
        b += __shfl_xor_sync(0xffffffffu, b, o);
    }
    __shared__ float sa[8], sb[8];
    __shared__ float s_inv;
    const int wid = tid >> 5, lane = tid & 31;
    if (lane == 0) { sa[wid] = a; sb[wid] = b; }
    __syncthreads();
    if (tid == 0) {
        float ta = 0.f, tb = 0.f;
#pragma unroll
        for (int i = 0; i < 8; i++) { ta += sa[i]; tb += sb[i]; }
        d_sq[row] = ta;
        s_inv = 1.0f / sqrtf(tb);
    }
    __syncthreads();
    d_ehat[row * F + tid] = e * s_inv;
}

// ---------------- symmetric fused GEMM — tf32 tensor cores --------------
// bid in [0, NBLK)      : K (fp16 out) = exp(-alpha*max(sq_i+sq_j-2*theta theta^T,0))
// bid in [NBLK, 2*NBLK) : Ghat (fp32 out) = ehat ehat^T
// 128x128 tile per block, 8 warps x (64x32) warp tiles of m16n8k8 tf32 mma.
// K-chunk = 64 -> 69.6KB smem -> 2 CTAs/SM -> single wave for all 272 blocks.
__global__ void __launch_bounds__(256, 2) gemm_sym(const float* __restrict__ theta) {
    extern __shared__ uint32_t smw[];
    uint32_t* As = smw;             // [128][PITCH2] tf32
    uint32_t* Bs = smw + TILEW2;    // [128][PITCH2] tf32

    const int bid = blockIdx.x;
    const bool modeK = (bid < NBLK);
    const int tb = modeK ? bid : bid - NBLK;
    const float* __restrict__ X = modeK ? theta : (const float*)d_ehat;

    // triangular index -> (ib, jb), ib >= jb
    int ib = (int)((sqrtf(8.0f * (float)tb + 1.0f) - 1.0f) * 0.5f);
    while ((ib + 1) * (ib + 2) / 2 <= tb) ib++;
    while (ib * (ib + 1) / 2 > tb) ib--;
    const int jb = tb - ib * (ib + 1) / 2;
    const int r0 = ib * 128, c0 = jb * 128;

    const int tid  = threadIdx.x;
    const int wid  = tid >> 5, lane = tid & 31;
    const int g    = lane >> 2, t = lane & 3;   // fragment group / thread-in-group
    const int wm   = wid >> 2,  wn = wid & 3;   // warp tile: rows wm*64, cols wn*32

    float c[4][4][4];
#pragma unroll
    for (int am = 0; am < 4; am++)
#pragma unroll
        for (int bn = 0; bn < 4; bn++)
#pragma unroll
            for (int e = 0; e < 4; e++) c[am][bn][e] = 0.0f;

    for (int kc = 0; kc < 4; kc++) {           // four 64-wide K chunks
        // stage: fp32 -> tf32 into padded smem (k-contiguous rows)
        for (int idx = tid; idx < 128 * 16; idx += 256) {
            const int r = idx >> 4, q = (idx & 15) * 4;
            const float4 av = *(const float4*)(X + (size_t)(r0 + r) * F + kc * 64 + q);
            uint4 ua;
            ua.x = f2tf32(av.x); ua.y = f2tf32(av.y);
            ua.z = f2tf32(av.z); ua.w = f2tf32(av.w);
            *(uint4*)&As[r * PITCH2 + q] = ua;
            const float4 bv = *(const float4*)(X + (size_t)(c0 + r) * F + kc * 64 + q);
            uint4 ub;
            ub.x = f2tf32(bv.x); ub.y = f2tf32(bv.y);
            ub.z = f2tf32(bv.z); ub.w = f2tf32(bv.w);
            *(uint4*)&Bs[r * PITCH2 + q] = ub;
        }
        __syncthreads();

#pragma unroll 4
        for (int s = 0; s < 8; s++) {          // k-steps of 8 within the chunk
            uint32_t a[4][4], b[4][2];
#pragma unroll
            for (int am = 0; am < 4; am++) {
                const uint32_t* p = As + (wm * 64 + am * 16 + g) * PITCH2 + s * 8 + t;
                a[am][0] = p[0];
                a[am][1] = p[8 * PITCH2];
                a[am][2] = p[4];
                a[am][3] = p[8 * PITCH2 + 4];
            }
#pragma unroll
            for (int bn = 0; bn < 4; bn++) {
                const uint32_t* p = Bs + (wn * 32 + bn * 8 + g) * PITCH2 + s * 8 + t;
                b[bn][0] = p[0];
                b[bn][1] = p[4];
            }
#pragma unroll
            for (int am = 0; am < 4; am++)
#pragma unroll
                for (int bn = 0; bn < 4; bn++)
                    mma_tf32(c[am][bn], a[am], b[bn]);
        }
        __syncthreads();                        // before next stage overwrites
    }

    // ---- epilogue: fragments -> smem (reuse whole region), then coalesced stores
    float* Ct = (float*)smw;                    // [128][PITCH_C]
#pragma unroll
    for (int am = 0; am < 4; am++) {
        const int r = wm * 64 + am * 16 + g;
#pragma unroll
        for (int bn = 0; bn < 4; bn++) {
            const int cc = wn * 32 + bn * 8 + 2 * t;
            *(float2*)&Ct[r * PITCH_C + cc]       = make_float2(c[am][bn][0], c[am][bn][1]);
            *(float2*)&Ct[(r + 8) * PITCH_C + cc] = make_float2(c[am][bn][2], c[am][bn][3]);
        }
    }
    __syncthreads();

    if (modeK) {
        // normal rows (coalesced)
        for (int idx = tid; idx < 128 * 32; idx += 256) {
            const int r = idx >> 5, q = (idx & 31) * 4;
            const float4 cv = *(const float4*)&Ct[r * PITCH_C + q];
            const float sr = __ldg(&d_sq[r0 + r]);
            union { __half h[4]; uint2 u; } pk;
            pk.h[0] = __float2half_rn(__expf(-ALPHA * fmaxf(sr + __ldg(&d_sq[c0 + q + 0]) - 2.0f * cv.x, 0.0f)));
            pk.h[1] = __float2half_rn(__expf(-ALPHA * fmaxf(sr + __ldg(&d_sq[c0 + q + 1]) - 2.0f * cv.y, 0.0f)));
            pk.h[2] = __float2half_rn(__expf(-ALPHA * fmaxf(sr + __ldg(&d_sq[c0 + q + 2]) - 2.0f * cv.z, 0.0f)));
            pk.h[3] = __float2half_rn(__expf(-ALPHA * fmaxf(sr + __ldg(&d_sq[c0 + q + 3]) - 2.0f * cv.w, 0.0f)));
            *(uint2*)(d_Kh + (size_t)(r0 + r) * D + c0 + q) = pk.u;
        }
        // mirror rows: lanes along m -> conflict-free column reads of Ct
        for (int idx = tid; idx < 128 * 32; idx += 256) {
            const int m = idx & 127, q = (idx >> 7) * 4;
            const float sm = __ldg(&d_sq[c0 + m]);
            union { __half h[4]; uint2 u; } pk;
#pragma unroll
            for (int e = 0; e < 4; e++) {
                const float v = Ct[(q + e) * PITCH_C + m];
                pk.h[e] = __float2half_rn(__expf(-ALPHA * fmaxf(sm + __ldg(&d_sq[r0 + q + e]) - 2.0f * v, 0.0f)));
            }
            *(uint2*)(d_Kh + (size_t)(c0 + m) * D + r0 + q) = pk.u;
        }
    } else {
        for (int idx = tid; idx < 128 * 32; idx += 256) {
            const int r = idx >> 5, q = (idx & 31) * 4;
            *(float4*)(d_G + (size_t)(r0 + r) * D + c0 + q) = *(const float4*)&Ct[r * PITCH_C + q];
        }
        for (int idx = tid; idx < 128 * 32; idx += 256) {
            const int m = idx & 127, q = (idx >> 7) * 4;
            float4 v;
            v.x = Ct[(q + 0) * PITCH_C + m];
            v.y = Ct[(q + 1) * PITCH_C + m];
            v.z = Ct[(q + 2) * PITCH_C + m];
            v.w = Ct[(q + 3) * PITCH_C + m];
            *(float4*)(d_G + (size_t)(c0 + m) * D + r0 + q) = v;
        }
    }
}

// ---------------- rowsum of Ghat -> invr ----------------
__global__ void __launch_bounds__(256) rowsum() {
    const int row  = blockIdx.x * 8 + (threadIdx.x >> 5);
    const int lane = threadIdx.x & 31;
    const float4* g = (const float4*)(d_G + (size_t)row * D);
    float s = 0.f;
#pragma unroll
    for (int it = 0; it < D / 128; it++) {
        const float4 v = g[lane + 32 * it];
        s += (v.x + v.y) + (v.z + v.w);
    }
    s = warp_red(s);
    if (lane == 0) d_invr[row] = 1.0f / s;
}

// two interleaved fp16 row-dots against smem fp32 vector, f32x2 accumulation
__device__ __forceinline__ void row_dot2h(const __half* __restrict__ K0,
                                          const __half* __restrict__ K1,
                                          const float* sx, int lane,
                                          float& o0, float& o1) {
    const uint4* a = (const uint4*)K0;   // 8 halves per uint4, 256 per row
    const uint4* b = (const uint4*)K1;
    ull s0a = 0ULL, s0b = 0ULL, s1a = 0ULL, s1b = 0ULL;
#pragma unroll
    for (int it = 0; it < 8; it++) {
        const int o = lane + 32 * it;
        const uint4 k0 = __ldg(a + o);
        const uint4 k1 = __ldg(b + o);
        const ulonglong2 x01 = *(const ulonglong2*)(sx + o * 8);
        const ulonglong2 x23 = *(const ulonglong2*)(sx + o * 8 + 4);
        fma2(s0a, h2f2(k0.x), x01.x); fma2(s0b, h2f2(k0.y), x01.y);
        fma2(s0a, h2f2(k0.z), x23.x); fma2(s0b, h2f2(k0.w), x23.y);
        fma2(s1a, h2f2(k1.x), x01.x); fma2(s1b, h2f2(k1.y), x01.y);
        fma2(s1a, h2f2(k1.z), x23.x); fma2(s1b, h2f2(k1.w), x23.y);
    }
    const float2 p0 = up2(s0a), q0 = up2(s0b);
    const float2 p1 = up2(s1a), q1 = up2(s1b);
    o0 = warp_red((p0.x + p0.y) + (q0.x + q0.y));
    o1 = warp_red((p1.x + p1.y) + (q1.x + q1.y));
}

// ---------------- persistent Sinkhorn (K symmetric => K^T u == K u) -------------
__global__ void __launch_bounds__(NT, 1) sinkhorn_kernel() {
    __shared__ float sx[D];
    __shared__ float sred[RPB];
    const int tid = threadIdx.x, bid = blockIdx.x;
    const int wid = tid >> 5, lane = tid & 31;
    const int row0 = bid * RPB + wid * 2;
    const float AB = 1.0f / (float)D;

    if (tid < RPB) { d_u[bid * RPB + tid] = 1.0f; d_v[bid * RPB + tid] = 1.0f; }

    unsigned ep = 1;
    gbar(ep * NB, tid); ep++;               // u,v init visible everywhere

    float err = 1.0f;
    int cpt = 0;
    while (err > STOPTHR && cpt < MAXIT) {
        // v = b / (K u + eps)
        for (int i = tid; i < D / 4; i += NT)
            ((float4*)sx)[i] = __ldcg(((const float4*)d_u) + i);
        __syncthreads();
        {
            float s0, s1;
            row_dot2h(d_Kh + (size_t)row0 * D, d_Kh + (size_t)(row0 + 1) * D, sx, lane, s0, s1);
            if (lane == 0) {
                d_v[row0]     = AB / (s0 + EPSF);
                d_v[row0 + 1] = AB / (s1 + EPSF);
            }
        }
        gbar(ep * NB, tid); ep++;

        // u = a / (K v + eps)
        for (int i = tid; i < D / 4; i += NT)
            ((float4*)sx)[i] = __ldcg(((const float4*)d_v) + i);
        __syncthreads();
        {
            float s0, s1;
            row_dot2h(d_Kh + (size_t)row0 * D, d_Kh + (size_t)(row0 + 1) * D, sx, lane, s0, s1);
            if (lane == 0) {
                d_u[row0]     = AB / (s0 + EPSF);
                d_u[row0 + 1] = AB / (s1 + EPSF);
            }
        }
        gbar(ep * NB, tid); ep++;

        cpt++;
        if (cpt % 50 == 1) {
            // err = sum_i | v_i * (K u_new)_i - b |
            for (int i = tid; i < D / 4; i += NT)
                ((float4*)sx)[i] = __ldcg(((const float4*)d_u) + i);
            __syncthreads();
            {
                float s0, s1;
                row_dot2h(d_Kh + (size_t)row0 * D, d_Kh + (size_t)(row0 + 1) * D, sx, lane, s0, s1);
                if (lane == 0) {
                    sred[wid * 2]     = fabsf(__ldcg(&d_v[row0])     * s0 - AB);
                    sred[wid * 2 + 1] = fabsf(__ldcg(&d_v[row0 + 1]) * s1 - AB);
                }
            }
            __syncthreads();
            const int chk = cpt / 50;
            if (tid == 0) {
                float e = 0.f;
#pragma unroll
                for (int i = 0; i < RPB; i++) e += sred[i];
                d_errpart[chk * NB + bid] = e;
            }
            gbar(ep * NB, tid); ep++;
            // every block reduces all 128 partials in the SAME order ->
            // identical float -> uniform exit. Saves one barrier vs broadcast.
            float e = 0.f;
            for (int i = 0; i < NB; i++) e += __ldcg(&d_errpart[chk * NB + i]);
            err = e;
        }
    }
}

// ---------------- KL reduction ----------------
// Qt_ij = max(u_i K_ij v_j, 1e-6), S = sum Qt, P_ij = G_ij*(invr_i+invr_j)/2
// kl = sum P*log(P/Qt) + log(S) * sum P
__global__ void __launch_bounds__(NT) kl_partial() {
    const int tid = threadIdx.x;
    constexpr int TOT8 = D * D / 8;
    const int stride = NKB * NT;
    const uint4*  Kv = (const uint4*)d_Kh;
    const float4* Gv = (const float4*)d_G;
    const float4* Vv = (const float4*)d_v;
    const float4* Rv = (const float4*)d_invr;

    float sS = 0.f, sP = 0.f, sK = 0.f;
    for (int g8 = blockIdx.x * NT + tid; g8 < TOT8; g8 += stride) {
        const int i  = g8 >> 8;
        const int c8 = g8 & 255;
        const uint4 kh = Kv[g8];
        const float4 g0 = Gv[g8 * 2];
        const float4 g1 = Gv[g8 * 2 + 1];
        const float4 v0 = Vv[c8 * 2];
        const float4 v1 = Vv[c8 * 2 + 1];
        const float4 r0 = Rv[c8 * 2];
        const float4 r1 = Rv[c8 * 2 + 1];
        const float ui  = d_u[i];
        const float iri = d_invr[i];

        const float2 ka = __half22float2(*(const __half2*)&kh.x);
        const float2 kb = __half22float2(*(const __half2*)&kh.y);
        const float2 kc = __half22float2(*(const __half2*)&kh.z);
        const float2 kd = __half22float2(*(const __half2*)&kh.w);

        float q, p;
        q = fmaxf(ui * ka.x * v0.x, 1e-6f); p = g0.x * (0.5f * (iri + r0.x));
        sS += q; sP += p; sK += p * __logf(__fdividef(p, q));
        q = fmaxf(ui * ka.y * v0.y, 1e-6f); p = g0.y * (0.5f * (iri + r0.y));
        sS += q; sP += p; sK += p * __logf(__fdividef(p, q));
        q = fmaxf(ui * kb.x * v0.z, 1e-6f); p = g0.z * (0.5f * (iri + r0.z));
        sS += q; sP += p; sK += p * __logf(__fdividef(p, q));
        q = fmaxf(ui * kb.y * v0.w, 1e-6f); p = g0.w * (0.5f * (iri + r0.w));
        sS += q; sP += p; sK += p * __logf(__fdividef(p, q));
        q = fmaxf(ui * kc.x * v1.x, 1e-6f); p = g1.x * (0.5f * (iri + r1.x));
        sS += q; sP += p; sK += p * __logf(__fdividef(p, q));
        q = fmaxf(ui * kc.y * v1.y, 1e-6f); p = g1.y * (0.5f * (iri + r1.y));
        sS += q; sP += p; sK += p * __logf(__fdividef(p, q));
        q = fmaxf(ui * kd.x * v1.z, 1e-6f); p = g1.z * (0.5f * (iri + r1.z));
        sS += q; sP += p; sK += p * __logf(__fdividef(p, q));
        q = fmaxf(ui * kd.y * v1.w, 1e-6f); p = g1.w * (0.5f * (iri + r1.w));
        sS += q; sP += p; sK += p * __logf(__fdividef(p, q));
    }

    __shared__ double sd[NT];
    const double vals[3] = {(double)sS, (double)sP, (double)sK};
#pragma unroll
    for (int t = 0; t < 3; t++) {
        sd[tid] = vals[t];
        __syncthreads();
        for (int o = NT / 2; o; o >>= 1) {
            if (tid < o) sd[tid] += sd[tid + o];
            __syncthreads();
        }
        if (tid == 0) d_part[t * NKB + blockIdx.x] = sd[0];
        __syncthreads();
    }
}

__global__ void __launch_bounds__(NKB) finalize(float* out) {
    __shared__ double sd[NKB];
    const int tid = threadIdx.x;
    double acc[3];
#pragma unroll
    for (int t = 0; t < 3; t++) {
        sd[tid] = d_part[t * NKB + tid];
        __syncthreads();
        for (int o = NKB / 2; o; o >>= 1) {
            if (tid < o) sd[tid] += sd[tid + o];
            __syncthreads();
        }
        acc[t] = sd[0];
        __syncthreads();
    }
    if (tid == 0) out[0] = (float)(acc[2] + log(acc[0]) * acc[1]);
}

// ---------------- launch ----------------
extern "C" void kernel_launch(void* const* d_in, const int* in_sizes, int n_in,
                              void* d_out, int out_size) {
    const float* theta = (const float*)d_in[0];
    const float* emb   = (const float*)d_in[1];
    float* out = (float*)d_out;

    cudaFuncSetAttribute((const void*)gemm_sym,
                         cudaFuncAttributeMaxDynamicSharedMemorySize, GEMM_SMEM);

    prep<<<D, F>>>(theta, emb);
    gemm_sym<<<2 * NBLK, 256, GEMM_SMEM>>>(theta);
    rowsum<<<D / 8, 256>>>();
    sinkhorn_kernel<<<NB, NT>>>();
    kl_partial<<<NKB, NT>>>();
    finalize<<<1, NKB>>>(out);
}